// round 6
// baseline (speedup 1.0000x reference)
#include <cuda_runtime.h>
#include <cuda_fp16.h>
#include <math.h>
#include <stdint.h>

// ---------------- problem constants ----------------
#define D_NODE 100
#define D_HID  300
#define NB     128
#define NT     512
#define NNODE  256
#define NLQ    256
#define ROWS_BT (NB*NT)     // 65536
#define ROWS_BN (NB*NNODE)  // 32768

#define KN_PAD 112          // 100 -> 112 (14 x 8-half segments)
#define KH_PAD 304          // 300 -> 304 (38 segments)

#define OUT_PATH   (NB*D_HID)
#define OUT_NODEF  ((long)ROWS_BN*D_HID)
#define OUT_TAIL_START (OUT_PATH + OUT_NODEF)

// ---------------- device scratch ----------------
__device__ __half g_nodes_h[(size_t)ROWS_BN * KN_PAD];
__device__ __half g_ctx_h[(size_t)NB * NLQ * KH_PAD];
__device__ __half g_Wc_h[1800 * KN_PAD];
__device__ __half g_Wnode_h[300 * KN_PAD];
__device__ __half g_Wout_h[300 * 600];
__device__ float  g_c[1800];
__device__ __half g_U_h[(size_t)ROWS_BN * 1800];
__device__ __half g_hidden_h[(size_t)ROWS_BT * 600];
__device__ __half g_hid_h[(size_t)ROWS_BT * KH_PAD];
__device__ __half g_scores_h[(size_t)NB * NLQ * NT];
__device__ float  g_alpha[NB * NT];

// ---------------- PTX helpers ----------------
__device__ __forceinline__ uint32_t smem_to_u32(const void* p) {
    uint32_t a;
    asm("{ .reg .u64 t; cvta.to.shared.u64 t, %1; cvt.u32.u64 %0, t; }" : "=r"(a) : "l"(p));
    return a;
}
__device__ __forceinline__ void mma_f16(float* d, const uint32_t* a, const uint32_t* b) {
    asm volatile(
        "mma.sync.aligned.m16n8k16.row.col.f32.f16.f16.f32 "
        "{%0,%1,%2,%3}, {%4,%5,%6,%7}, {%8,%9}, {%0,%1,%2,%3};"
        : "+f"(d[0]), "+f"(d[1]), "+f"(d[2]), "+f"(d[3])
        : "r"(a[0]), "r"(a[1]), "r"(a[2]), "r"(a[3]), "r"(b[0]), "r"(b[1]));
}
__device__ __forceinline__ void ldsm_x4(uint32_t* r, uint32_t addr) {
    asm volatile("ldmatrix.sync.aligned.m8n8.x4.shared.b16 {%0,%1,%2,%3}, [%4];"
        : "=r"(r[0]), "=r"(r[1]), "=r"(r[2]), "=r"(r[3]) : "r"(addr));
}
__device__ __forceinline__ void cp_async16(uint32_t dst, const void* src, int src_size) {
    asm volatile("cp.async.cg.shared.global [%0], [%1], 16, %2;"
        :: "r"(dst), "l"(src), "r"(src_size) : "memory");
}
#define CP_COMMIT() asm volatile("cp.async.commit_group;" ::: "memory")
#define CP_WAIT(n)  asm volatile("cp.async.wait_group %0;" :: "n"(n) : "memory")

__device__ __forceinline__ float fexp2(float x) {
    float y; asm("ex2.approx.f32 %0, %1;" : "=f"(y) : "f"(x)); return y;
}
__device__ __forceinline__ float frcp(float x) {
    float y; asm("rcp.approx.f32 %0, %1;" : "=f"(y) : "f"(x)); return y;
}
#define LOG2E 1.4426950408889634f
__device__ __forceinline__ float fsigmoid(float x) { return frcp(1.f + fexp2(-LOG2E * x)); }
__device__ __forceinline__ float ftanh(float x)    { return 2.f * frcp(1.f + fexp2(-2.f * LOG2E * x)) - 1.f; }

// ================= fp16 mma.sync GEMM (ldmatrix mainloop) =================
// C[m,n] = act( sum_k A[m,k]*W[n,k] + bias[n] ). A:[M,K] rm fp16, W:[N,K] rm fp16.
// K multiple of 8 (padded, pad zeroed). M % 128 == 0. N even.
// OUT_HALF: C fp16 with row stride Npad (cols [N,Npad) zero-filled); else fp32, stride N.
#define BM 128
#define BN 128
#define ASTR 40                                 // smem row stride in halves (80B; ldmatrix conflict-free)

template <bool OUT_HALF>
__global__ void __launch_bounds__(256, 2)
gemm_f16(const __half* __restrict__ A, long aBatch,
         const __half* __restrict__ W, long wBatch,
         void* __restrict__ Cv, long cBatch,
         int M, int N, int Npad, int K,
         const float* __restrict__ bias, int act_tanh)
{
    __shared__ __half sA[2][BM * ASTR];
    __shared__ __half sB[2][BN * ASTR];

    const int bz = blockIdx.z;
    A += (long)bz * aBatch; W += (long)bz * wBatch;

    const int tid  = threadIdx.x;
    const int warp = tid >> 5, lane = tid & 31;
    const int wm = warp & 3, wn = warp >> 2;     // 4 x 2 warp grid
    const int g = lane >> 2, t = lane & 3;

    const int m0 = blockIdx.y * BM;
    const int n0 = blockIdx.x * BN;
    const int CH = (K + 31) >> 5;

    const uint32_t sA32 = smem_to_u32(sA);
    const uint32_t sB32 = smem_to_u32(sB);

    // ldmatrix lane address components
    const int lr  = lane & 15;                   // A: row within 16
    const int lc8 = (lane >> 4) * 8;             // A: k offset 0/8
    const int bn_ = (lane & 7) + ((lane >> 4) << 3);  // B: n offset within 16-row pair group
    const int bk8 = lane & 8;                    // B: k offset 0/8

    float acc[2][8][4];
#pragma unroll
    for (int i = 0; i < 2; ++i)
#pragma unroll
        for (int j = 0; j < 8; ++j)
#pragma unroll
            for (int q = 0; q < 4; ++q) acc[i][j][q] = 0.f;

    auto issue = [&](int c) {
        const int s = c & 1;
        const int kb = c << 5;
        const uint32_t aB = sA32 + (uint32_t)s * (BM * ASTR * 2);
        const uint32_t bB = sB32 + (uint32_t)s * (BN * ASTR * 2);
#pragma unroll
        for (int i = 0; i < 2; ++i) {
            const int seg = tid + i * 256;       // 0..511
            const int row = seg >> 2, q = seg & 3;
            const int k = kb + q * 8;
            const int va = (k + 8 <= K);
            cp_async16(aB + (uint32_t)(row * (ASTR * 2) + q * 16),
                       va ? (const void*)(A + (long)(m0 + row) * K + k) : (const void*)A,
                       va ? 16 : 0);
            const int vb = va && (n0 + row < N);
            cp_async16(bB + (uint32_t)(row * (ASTR * 2) + q * 16),
                       vb ? (const void*)(W + (long)(n0 + row) * K + k) : (const void*)W,
                       vb ? 16 : 0);
        }
        CP_COMMIT();
    };

    issue(0);
    for (int c = 0; c < CH; ++c) {
        if (c + 1 < CH) { issue(c + 1); CP_WAIT(1); }
        else            { CP_WAIT(0); }
        __syncthreads();

        const uint32_t aBuf = sA32 + (uint32_t)(c & 1) * (BM * ASTR * 2);
        const uint32_t bBuf = sB32 + (uint32_t)(c & 1) * (BN * ASTR * 2);

        uint32_t aAddr[2], bAddr[4];
#pragma unroll
        for (int tm = 0; tm < 2; ++tm)
            aAddr[tm] = aBuf + (uint32_t)(((wm * 32 + tm * 16 + lr) * ASTR + lc8) * 2);
#pragma unroll
        for (int p = 0; p < 4; ++p)
            bAddr[p] = bBuf + (uint32_t)(((wn * 64 + p * 16 + bn_) * ASTR + bk8) * 2);

#pragma unroll
        for (int kk = 0; kk < 2; ++kk) {         // two k16 steps per 32-k chunk
            uint32_t af[2][4], bf[8][2];
            ldsm_x4(af[0], aAddr[0] + kk * 32);
            ldsm_x4(af[1], aAddr[1] + kk * 32);
#pragma unroll
            for (int p = 0; p < 4; ++p) {
                uint32_t r[4];
                ldsm_x4(r, bAddr[p] + kk * 32);
                bf[2 * p][0]     = r[0];
                bf[2 * p][1]     = r[1];
                bf[2 * p + 1][0] = r[2];
                bf[2 * p + 1][1] = r[3];
            }
#pragma unroll
            for (int tm = 0; tm < 2; ++tm)
#pragma unroll
                for (int tn = 0; tn < 8; ++tn)
                    mma_f16(acc[tm][tn], af[tm], bf[tn]);
        }
        __syncthreads();
    }

    // epilogue
#pragma unroll
    for (int tm = 0; tm < 2; ++tm) {
        const int row = m0 + wm * 32 + tm * 16 + g;
#pragma unroll
        for (int tn = 0; tn < 8; ++tn) {
            const int n = n0 + wn * 64 + tn * 8 + 2 * t;
            if (OUT_HALF ? (n < Npad) : (n < N)) {
                float v0 = 0.f, v1 = 0.f, v2 = 0.f, v3 = 0.f;
                if (n < N) {
                    float b0 = 0.f, b1 = 0.f;
                    if (bias) { b0 = bias[n]; b1 = bias[n + 1]; }
                    v0 = acc[tm][tn][0] + b0;
                    v1 = acc[tm][tn][1] + b1;
                    v2 = acc[tm][tn][2] + b0;
                    v3 = acc[tm][tn][3] + b1;
                    if (act_tanh) { v0 = ftanh(v0); v1 = ftanh(v1); v2 = ftanh(v2); v3 = ftanh(v3); }
                }
                if constexpr (OUT_HALF) {
                    __half* C = (__half*)Cv + (long)bz * cBatch;
                    *(__half2*)(C + (size_t)row * Npad + n)       = __floats2half2_rn(v0, v1);
                    *(__half2*)(C + (size_t)(row + 8) * Npad + n) = __floats2half2_rn(v2, v3);
                } else {
                    float* C = (float*)Cv + (long)bz * cBatch;
                    *(float2*)(C + (size_t)row * N + n)       = make_float2(v0, v1);
                    *(float2*)(C + (size_t)(row + 8) * N + n) = make_float2(v2, v3);
                }
            }
        }
    }
}

// ---------------- fp32 -> fp16 convert with row padding ----------------
__global__ void convert_pad(const float* __restrict__ src, __half* __restrict__ dst,
                            int rows, int K, int Kpad)
{
    const int total = rows * Kpad;
    for (int i = blockIdx.x * blockDim.x + threadIdx.x; i < total; i += gridDim.x * blockDim.x) {
        const int r = i / Kpad, k = i - r * Kpad;
        dst[i] = __float2half((k < K) ? src[(size_t)r * K + k] : 0.f);
    }
}

// ---------------- weight combine -> fp16 Wc (padded) + fp32 c ----------------
#define CBJ 16
#define COMBINE_SMEM ((30000 + CBJ * 300) * 4)

__global__ void __launch_bounds__(256)
combine_kernel(const float* __restrict__ Wf, const float* __restrict__ bif,
               const float* __restrict__ bhf,
               const float* __restrict__ Wb, const float* __restrict__ bib,
               const float* __restrict__ bhb,
               const float* __restrict__ Wmean, const float* __restrict__ bmean)
{
    extern __shared__ float csm[];
    float* sW   = csm;            // [300*100]
    float* srow = csm + 30000;    // [CBJ][300]

    const int j0 = blockIdx.x * CBJ;
    const int tid = threadIdx.x;

    for (int i = tid; i < 30000; i += 256) sW[i] = Wmean[i];
    for (int i = tid; i < CBJ * 300; i += 256) {
        const int jj = i / 300, d = i % 300, j = j0 + jj;
        float v = 0.f;
        if (j < 1800) v = (j < 900) ? Wf[j * 300 + d] : Wb[(j - 900) * 300 + d];
        srow[i] = v;
    }
    __syncthreads();

    for (int idx = tid; idx < CBJ * KN_PAD; idx += 256) {
        const int jj = idx / KN_PAD, k = idx % KN_PAD, j = j0 + jj;
        if (j >= 1800) continue;
        float s = 0.f;
        if (k < 100) {
            const float* wr = srow + jj * 300;
#pragma unroll 4
            for (int d = 0; d < 300; ++d) s = fmaf(wr[d], sW[d * 100 + k], s);
        }
        g_Wc_h[j * KN_PAD + k] = __float2half(s);
    }
    if (tid < CBJ) {
        const int j = j0 + tid;
        if (j < 1800) {
            const int fwd = (j < 900), jj2 = fwd ? j : j - 900;
            const float* bih = fwd ? bif : bib;
            const float* bhh = fwd ? bhf : bhb;
            const float* wr = srow + tid * 300;
            float s = bih[jj2];
            for (int d = 0; d < 300; ++d) s = fmaf(wr[d], bmean[d], s);
            if (jj2 < 600) s += bhh[jj2];
            g_c[j] = s;
        }
    }
}

// ---------------- GRU gates: read fp16 U, write fp16 hidden ----------------
__device__ __forceinline__ float4 h4_to_f4(const __half* p) {
    uint2 v = *(const uint2*)p;
    __half2 h0 = *reinterpret_cast<__half2*>(&v.x);
    __half2 h1 = *reinterpret_cast<__half2*>(&v.y);
    float2 f0 = __half22float2(h0), f1 = __half22float2(h1);
    return make_float4(f0.x, f0.y, f1.x, f1.y);
}
__device__ __forceinline__ float4 avg4(float4 a, float4 b) {
    return make_float4(0.5f * (a.x + b.x), 0.5f * (a.y + b.y),
                       0.5f * (a.z + b.z), 0.5f * (a.w + b.w));
}
__global__ void __launch_bounds__(160) gates_kernel(const int* __restrict__ tri,
                                                    const float* __restrict__ bhf,
                                                    const float* __restrict__ bhb)
{
    const int bt = blockIdx.x;
    const int b = bt >> 9;
    const int h = tri[bt * 3 + 0];
    const int t = tri[bt * 3 + 2];
    const __half* uh = g_U_h + (size_t)(b * NNODE + h) * 1800;
    const __half* ut = g_U_h + (size_t)(b * NNODE + t) * 1800;
    __half* out = g_hidden_h + (size_t)bt * 600;

    const int tid = threadIdx.x;
    int grp, j;
    if (tid < 75)                    { grp = 0; j = tid; }
    else if (tid >= 80 && tid < 155) { grp = 1; j = tid - 80; }
    else return;

    const int base = grp * 900 + 4 * j;          // half index
    const float* bh = grp ? bhb : bhf;
    const float4 r4 = avg4(h4_to_f4(uh + base),       h4_to_f4(ut + base));
    const float4 z4 = avg4(h4_to_f4(uh + base + 300), h4_to_f4(ut + base + 300));
    const float4 n4 = avg4(h4_to_f4(uh + base + 600), h4_to_f4(ut + base + 600));
    const float4 bb = ((const float4*)(bh + 600))[j];

    float4 o;
    o.x = (1.f - fsigmoid(z4.x)) * ftanh(n4.x + fsigmoid(r4.x) * bb.x);
    o.y = (1.f - fsigmoid(z4.y)) * ftanh(n4.y + fsigmoid(r4.y) * bb.y);
    o.z = (1.f - fsigmoid(z4.z)) * ftanh(n4.z + fsigmoid(r4.z) * bb.z);
    o.w = (1.f - fsigmoid(z4.w)) * ftanh(n4.w + fsigmoid(r4.w) * bb.w);

    __half2 h0 = __floats2half2_rn(o.x, o.y);
    __half2 h1 = __floats2half2_rn(o.z, o.w);
    uint2 v;
    v.x = *reinterpret_cast<uint32_t*>(&h0);
    v.y = *reinterpret_cast<uint32_t*>(&h1);
    *(uint2*)(out + grp * 300 + 4 * j) = v;
}

// ---------------- single-pass softmax over t per (b,l) + alpha[b,t] = sum_l ----------------
__global__ void __launch_bounds__(512) softmax_alpha_kernel()
{
    const int b = blockIdx.x;
    const __half* S = g_scores_h + (size_t)b * NLQ * NT;
    __shared__ float part[16][NT];               // 32 KB

    const int tid = threadIdx.x;
    const int w = tid >> 5, lane = tid & 31;

    float pacc[16];
#pragma unroll
    for (int q = 0; q < 16; ++q) pacc[q] = 0.f;

    for (int l = w; l < NLQ; l += 16) {
        const __half2* row2 = (const __half2*)(S + (size_t)l * NT);
        float v[16], m = -1e30f;
#pragma unroll
        for (int q = 0; q < 8; ++q) {
            float2 f = __half22float2(row2[lane + 32 * q]);
            v[2 * q] = f.x; v[2 * q + 1] = f.y;
            m = fmaxf(m, fmaxf(f.x, f.y));
        }
#pragma unroll
        for (int o = 16; o; o >>= 1) m = fmaxf(m, __shfl_xor_sync(0xffffffffu, m, o));
        float e[16], s = 0.f;
#pragma unroll
        for (int q = 0; q < 16; ++q) { e[q] = fexp2(LOG2E * (v[q] - m)); s += e[q]; }
#pragma unroll
        for (int o = 16; o; o >>= 1) s += __shfl_xor_sync(0xffffffffu, s, o);
        const float rinv = frcp(s);
#pragma unroll
        for (int q = 0; q < 16; ++q) pacc[q] += e[q] * rinv;
    }
#pragma unroll
    for (int q = 0; q < 8; ++q) {
        const int c = 2 * (lane + 32 * q);
        part[w][c]     = pacc[2 * q];
        part[w][c + 1] = pacc[2 * q + 1];
    }
    __syncthreads();

    float s = 0.f;
#pragma unroll
    for (int w2 = 0; w2 < 16; ++w2) s += part[w2][tid];
    g_alpha[b * NT + tid] = s;
}

// ---------------- rep = alpha @ hid_ ; layernorm ----------------
__global__ void __launch_bounds__(320) rep_ln_kernel(const float* __restrict__ gamma,
                                                     const float* __restrict__ beta,
                                                     float* __restrict__ out)
{
    const int b = blockIdx.x;
    __shared__ float sal[NT];
    __shared__ float red[2][10];
    const int tid = threadIdx.x;

    for (int t = tid; t < NT; t += 320) sal[t] = g_alpha[b * NT + t];
    __syncthreads();

    float acc = 0.f;
    const __half* H = g_hid_h + (size_t)b * NT * KH_PAD;
    if (tid < D_HID) {
        for (int t = 0; t < NT; ++t)
            acc = fmaf(sal[t], __half2float(H[(size_t)t * KH_PAD + tid]), acc);
    }
    float v1 = (tid < D_HID) ? acc : 0.f;
    float v2 = (tid < D_HID) ? acc * acc : 0.f;
#pragma unroll
    for (int o = 16; o; o >>= 1) {
        v1 += __shfl_xor_sync(0xffffffffu, v1, o);
        v2 += __shfl_xor_sync(0xffffffffu, v2, o);
    }
    const int wid = tid >> 5, lane = tid & 31;
    if (lane == 0) { red[0][wid] = v1; red[1][wid] = v2; }
    __syncthreads();
    if (tid == 0) {
        float s1 = 0.f, s2 = 0.f;
        for (int w = 0; w < 10; ++w) { s1 += red[0][w]; s2 += red[1][w]; }
        red[0][0] = s1 / (float)D_HID;
        red[1][0] = s2 / (float)D_HID;
    }
    __syncthreads();
    if (tid < D_HID) {
        float mu = red[0][0];
        float var = red[1][0] - mu * mu;
        out[b * D_HID + tid] = (acc - mu) * rsqrtf(var + 1e-5f) * gamma[tid] + beta[tid];
    }
}

__global__ void zero_tail_kernel(float* __restrict__ out, long start, long end)
{
    long i = start + (long)blockIdx.x * blockDim.x + threadIdx.x;
    if (i < end) out[i] = 0.f;
}

// ---------------- launch ----------------
extern "C" void kernel_launch(void* const* d_in, const int* in_sizes, int n_in,
                              void* d_out, int out_size)
{
    const int o = (in_sizes[3] == 1) ? 1 : 0;

    const float* nodes  = (const float*)d_in[0];
    const float* ctx    = (const float*)d_in[1];
    const int*   tri    = (const int*)d_in[2];
    const float* W_mean = (const float*)d_in[3 + o];
    const float* b_mean = (const float*)d_in[4 + o];
    const float* W_ih_f = (const float*)d_in[5 + o];
    const float* b_ih_f = (const float*)d_in[6 + o];
    const float* b_hh_f = (const float*)d_in[7 + o];
    const float* W_ih_b = (const float*)d_in[8 + o];
    const float* b_ih_b = (const float*)d_in[9 + o];
    const float* b_hh_b = (const float*)d_in[10 + o];
    const float* W_out  = (const float*)d_in[11 + o];
    const float* b_out  = (const float*)d_in[12 + o];
    const float* W_node = (const float*)d_in[13 + o];
    const float* b_node = (const float*)d_in[14 + o];
    const float* gamma  = (const float*)d_in[15 + o];
    const float* beta   = (const float*)d_in[16 + o];
    float* out = (float*)d_out;

    __half *pNodesH, *pCtxH, *pWcH, *pWnodeH, *pWoutH, *pUH, *pHiddenH, *pHidH, *pScoresH;
    float* pC;
    cudaGetSymbolAddress((void**)&pNodesH,  g_nodes_h);
    cudaGetSymbolAddress((void**)&pCtxH,    g_ctx_h);
    cudaGetSymbolAddress((void**)&pWcH,     g_Wc_h);
    cudaGetSymbolAddress((void**)&pWnodeH,  g_Wnode_h);
    cudaGetSymbolAddress((void**)&pWoutH,   g_Wout_h);
    cudaGetSymbolAddress((void**)&pC,       g_c);
    cudaGetSymbolAddress((void**)&pUH,      g_U_h);
    cudaGetSymbolAddress((void**)&pHiddenH, g_hidden_h);
    cudaGetSymbolAddress((void**)&pHidH,    g_hid_h);
    cudaGetSymbolAddress((void**)&pScoresH, g_scores_h);

    cudaFuncSetAttribute(combine_kernel, cudaFuncAttributeMaxDynamicSharedMemorySize, COMBINE_SMEM);

    // 0. fp16 conversions (padded)
    convert_pad<<<4096, 256>>>(nodes,  pNodesH, ROWS_BN, D_NODE, KN_PAD);
    convert_pad<<<8192, 256>>>(ctx,    pCtxH,   NB * NLQ, D_HID, KH_PAD);
    convert_pad<<<132,  256>>>(W_node, pWnodeH, D_HID, D_NODE, KN_PAD);
    convert_pad<<<704,  256>>>(W_out,  pWoutH,  D_HID, 600, 600);

    // 1. combined weights/biases
    combine_kernel<<<(1800 + CBJ - 1) / CBJ, 256, COMBINE_SMEM>>>(
        W_ih_f, b_ih_f, b_hh_f, W_ih_b, b_ih_b, b_hh_b, W_mean, b_mean);

    // 2. U[32768,1800] = nodes @ Wc^T + c   (fp16 out)
    {
        dim3 grid((1800 + BN - 1) / BN, ROWS_BN / BM, 1);
        gemm_f16<true><<<grid, 256>>>(pNodesH, 0, pWcH, 0, pUH, 0,
                                      ROWS_BN, 1800, 1800, KN_PAD, pC, 0);
    }
    // 3. node_feature[32768,300] = nodes @ W_node^T + b_node   (fp32 out, final)
    {
        dim3 grid((D_HID + BN - 1) / BN, ROWS_BN / BM, 1);
        gemm_f16<false><<<grid, 256>>>(pNodesH, 0, pWnodeH, 0, out + OUT_PATH, 0,
                                       ROWS_BN, D_HID, D_HID, KN_PAD, b_node, 0);
    }
    // 4. GRU gates -> hidden[65536,600] fp16
    gates_kernel<<<ROWS_BT, 160>>>(tri, b_hh_f, b_hh_b);

    // 5. hid_[65536,304] = tanh(hidden @ W_out^T + b_out)   (fp16 out, padded)
    {
        dim3 grid((KH_PAD + BN - 1) / BN, ROWS_BT / BM, 1);
        gemm_f16<true><<<grid, 256>>>(pHiddenH, 0, pWoutH, 0, pHidH, 0,
                                      ROWS_BT, D_HID, KH_PAD, 600, b_out, 1);
    }
    // 6. scores[b,256,512] = ctx[b] @ hid_[b]^T   (fp16 out)
    {
        dim3 grid(NT / BN, NLQ / BM, NB);
        gemm_f16<true><<<grid, 256>>>(pCtxH, (long)NLQ * KH_PAD,
                                      pHidH, (long)NT * KH_PAD,
                                      pScoresH, (long)NLQ * NT,
                                      NLQ, NT, NT, KH_PAD, nullptr, 0);
    }
    // 7. single-pass softmax/alpha
    softmax_alpha_kernel<<<NB, 512>>>();
    // 8. rep + layernorm
    rep_ln_kernel<<<NB, 320>>>(gamma, beta, out);
    // 9. node_mask zeros
    {
        long start = OUT_TAIL_START;
        long end = (long)out_size;
        if (end > start) {
            long n = end - start;
            int blocks = (int)((n + 255) / 256);
            zero_tail_kernel<<<blocks, 256>>>(out, start, end);
        }
    }
}

// round 7
// speedup vs baseline: 1.4361x; 1.4361x over previous
#include <cuda_runtime.h>
#include <cuda_fp16.h>
#include <math.h>
#include <stdint.h>

// ---------------- problem constants ----------------
#define D_NODE 100
#define D_HID  300
#define NB     128
#define NT     512
#define NNODE  256
#define NLQ    256
#define ROWS_BT (NB*NT)     // 65536
#define ROWS_BN (NB*NNODE)  // 32768

#define KN_PAD 112          // 100 -> 112 (14 x 8-half segments)
#define KH_PAD 304          // 300 -> 304 (38 segments)

#define OUT_PATH   (NB*D_HID)
#define OUT_NODEF  ((long)ROWS_BN*D_HID)
#define OUT_TAIL_START (OUT_PATH + OUT_NODEF)

// ---------------- device scratch ----------------
__device__ __half g_nodes_h[(size_t)ROWS_BN * KN_PAD];
__device__ __half g_ctx_h[(size_t)NB * NLQ * KH_PAD];
__device__ __half g_Wc_h[1800 * KN_PAD];
__device__ __half g_Wnode_h[300 * KN_PAD];
__device__ __half g_Wout_h[300 * 600];
__device__ float  g_c[1800];
__device__ __half g_U_h[(size_t)ROWS_BN * 1800];
__device__ __half g_hidden_h[(size_t)ROWS_BT * 600];
__device__ __half g_hid_h[(size_t)ROWS_BT * KH_PAD];
__device__ __half g_scores_h[(size_t)NB * NLQ * NT];
__device__ float  g_alpha[NB * NT];

// ---------------- PTX helpers ----------------
__device__ __forceinline__ uint32_t smem_to_u32(const void* p) {
    uint32_t a;
    asm("{ .reg .u64 t; cvta.to.shared.u64 t, %1; cvt.u32.u64 %0, t; }" : "=r"(a) : "l"(p));
    return a;
}
__device__ __forceinline__ void mma_f16(float* d, const uint32_t* a, const uint32_t* b) {
    asm volatile(
        "mma.sync.aligned.m16n8k16.row.col.f32.f16.f16.f32 "
        "{%0,%1,%2,%3}, {%4,%5,%6,%7}, {%8,%9}, {%0,%1,%2,%3};"
        : "+f"(d[0]), "+f"(d[1]), "+f"(d[2]), "+f"(d[3])
        : "r"(a[0]), "r"(a[1]), "r"(a[2]), "r"(a[3]), "r"(b[0]), "r"(b[1]));
}
__device__ __forceinline__ void cp_async16(uint32_t dst, const void* src, int src_size) {
    asm volatile("cp.async.cg.shared.global [%0], [%1], 16, %2;"
        :: "r"(dst), "l"(src), "r"(src_size) : "memory");
}
#define CP_COMMIT() asm volatile("cp.async.commit_group;" ::: "memory")
#define CP_WAIT(n)  asm volatile("cp.async.wait_group %0;" :: "n"(n) : "memory")

__device__ __forceinline__ float fexp2(float x) {
    float y; asm("ex2.approx.f32 %0, %1;" : "=f"(y) : "f"(x)); return y;
}
__device__ __forceinline__ float frcp(float x) {
    float y; asm("rcp.approx.f32 %0, %1;" : "=f"(y) : "f"(x)); return y;
}
#define LOG2E 1.4426950408889634f
__device__ __forceinline__ float fsigmoid(float x) { return frcp(1.f + fexp2(-LOG2E * x)); }
__device__ __forceinline__ float ftanh(float x)    { return 2.f * frcp(1.f + fexp2(-2.f * LOG2E * x)) - 1.f; }

// ================= fp16 mma.sync GEMM (4-stage cp.async pipeline) =================
// C[m,n] = act( sum_k A[m,k]*W[n,k] + bias[n] ). A:[M,K] rm fp16, W:[N,K] rm fp16.
// K multiple of 8 (padded, pad zeroed). M % 128 == 0. N even.
// OUT_HALF: C fp16 with row stride Npad (cols [N,Npad) zero-filled); else fp32, stride N.
#define BM 128
#define BN 128
#define ASTR 40                                 // smem row stride in halves
#define NSTAGE 4
#define STAGE_HALVES ((BM + BN) * ASTR)         // 10240 halves = 20480 B
#define GEMM_SMEM_BYTES (NSTAGE * STAGE_HALVES * 2)   // 81920

template <bool OUT_HALF>
__global__ void __launch_bounds__(256, 2)
gemm_f16(const __half* __restrict__ A, long aBatch,
         const __half* __restrict__ W, long wBatch,
         void* __restrict__ Cv, long cBatch,
         int M, int N, int Npad, int K,
         const float* __restrict__ bias, int act_tanh)
{
    extern __shared__ __half dsm[];

    const int bz = blockIdx.z;
    A += (long)bz * aBatch; W += (long)bz * wBatch;

    const int tid  = threadIdx.x;
    const int warp = tid >> 5, lane = tid & 31;
    const int wm = warp & 3, wn = warp >> 2;     // 4 x 2 warp grid
    const int g = lane >> 2, t = lane & 3;

    const int m0 = blockIdx.y * BM;
    const int n0 = blockIdx.x * BN;
    const int CH = (K + 31) >> 5;

    const uint32_t sm32 = smem_to_u32(dsm);

    float acc[2][8][4];
#pragma unroll
    for (int i = 0; i < 2; ++i)
#pragma unroll
        for (int j = 0; j < 8; ++j)
#pragma unroll
            for (int q = 0; q < 4; ++q) acc[i][j][q] = 0.f;

    auto issue = [&](int c) {
        const int s = c & (NSTAGE - 1);
        const int kb = c << 5;
        const uint32_t aB = sm32 + (uint32_t)s * (STAGE_HALVES * 2);
        const uint32_t bB = aB + (uint32_t)(BM * ASTR * 2);
#pragma unroll
        for (int i = 0; i < 2; ++i) {
            const int seg = tid + i * 256;       // 0..511
            const int row = seg >> 2, q = seg & 3;
            const int k = kb + q * 8;
            const int va = (k + 8 <= K);
            cp_async16(aB + (uint32_t)(row * (ASTR * 2) + q * 16),
                       va ? (const void*)(A + (long)(m0 + row) * K + k) : (const void*)A,
                       va ? 16 : 0);
            const int vb = va && (n0 + row < N);
            cp_async16(bB + (uint32_t)(row * (ASTR * 2) + q * 16),
                       vb ? (const void*)(W + (long)(n0 + row) * K + k) : (const void*)W,
                       vb ? 16 : 0);
        }
        CP_COMMIT();
    };

    // prologue: stages 0..NSTAGE-2 (empty commits keep group accounting uniform)
#pragma unroll
    for (int s = 0; s < NSTAGE - 1; ++s) {
        if (s < CH) issue(s);
        else        CP_COMMIT();
    }

#pragma unroll 1
    for (int c = 0; c < CH; ++c) {
        if (c + NSTAGE - 1 < CH) issue(c + NSTAGE - 1);
        else                     CP_COMMIT();
        CP_WAIT(NSTAGE - 1);                     // group c retired
        __syncthreads();

        const __half* a_ = dsm + (size_t)(c & (NSTAGE - 1)) * STAGE_HALVES;
        const __half* b_ = a_ + BM * ASTR;

#pragma unroll
        for (int kk = 0; kk < 2; ++kk) {         // two k16 steps per 32-k chunk
            const int col = kk * 16 + 2 * t;
            uint32_t af[2][4], bf[8][2];
#pragma unroll
            for (int tm = 0; tm < 2; ++tm) {
                const int r = wm * 32 + tm * 16 + g;
                af[tm][0] = *(const uint32_t*)(a_ + r * ASTR + col);
                af[tm][1] = *(const uint32_t*)(a_ + (r + 8) * ASTR + col);
                af[tm][2] = *(const uint32_t*)(a_ + r * ASTR + col + 8);
                af[tm][3] = *(const uint32_t*)(a_ + (r + 8) * ASTR + col + 8);
            }
#pragma unroll
            for (int tn = 0; tn < 8; ++tn) {
                const int n = wn * 64 + tn * 8 + g;
                bf[tn][0] = *(const uint32_t*)(b_ + n * ASTR + col);
                bf[tn][1] = *(const uint32_t*)(b_ + n * ASTR + col + 8);
            }
#pragma unroll
            for (int tm = 0; tm < 2; ++tm)
#pragma unroll
                for (int tn = 0; tn < 8; ++tn)
                    mma_f16(acc[tm][tn], af[tm], bf[tn]);
        }
        __syncthreads();
    }

    // epilogue
#pragma unroll
    for (int tm = 0; tm < 2; ++tm) {
        const int row = m0 + wm * 32 + tm * 16 + g;
#pragma unroll
        for (int tn = 0; tn < 8; ++tn) {
            const int n = n0 + wn * 64 + tn * 8 + 2 * t;
            if (OUT_HALF ? (n < Npad) : (n < N)) {
                float v0 = 0.f, v1 = 0.f, v2 = 0.f, v3 = 0.f;
                if (n < N) {
                    float b0 = 0.f, b1 = 0.f;
                    if (bias) { b0 = bias[n]; b1 = bias[n + 1]; }
                    v0 = acc[tm][tn][0] + b0;
                    v1 = acc[tm][tn][1] + b1;
                    v2 = acc[tm][tn][2] + b0;
                    v3 = acc[tm][tn][3] + b1;
                    if (act_tanh) { v0 = ftanh(v0); v1 = ftanh(v1); v2 = ftanh(v2); v3 = ftanh(v3); }
                }
                if constexpr (OUT_HALF) {
                    __half* C = (__half*)Cv + (long)bz * cBatch;
                    *(__half2*)(C + (size_t)row * Npad + n)       = __floats2half2_rn(v0, v1);
                    *(__half2*)(C + (size_t)(row + 8) * Npad + n) = __floats2half2_rn(v2, v3);
                } else {
                    float* C = (float*)Cv + (long)bz * cBatch;
                    *(float2*)(C + (size_t)row * N + n)       = make_float2(v0, v1);
                    *(float2*)(C + (size_t)(row + 8) * N + n) = make_float2(v2, v3);
                }
            }
        }
    }
}

// ---------------- fp32 -> fp16 convert with row padding ----------------
__global__ void convert_pad(const float* __restrict__ src, __half* __restrict__ dst,
                            int rows, int K, int Kpad)
{
    const int total = rows * Kpad;
    for (int i = blockIdx.x * blockDim.x + threadIdx.x; i < total; i += gridDim.x * blockDim.x) {
        const int r = i / Kpad, k = i - r * Kpad;
        dst[i] = __float2half((k < K) ? src[(size_t)r * K + k] : 0.f);
    }
}

// ---------------- weight combine -> fp16 Wc (padded) + fp32 c ----------------
#define CBJ 16
#define COMBINE_SMEM ((30000 + CBJ * 300) * 4)

__global__ void __launch_bounds__(256)
combine_kernel(const float* __restrict__ Wf, const float* __restrict__ bif,
               const float* __restrict__ bhf,
               const float* __restrict__ Wb, const float* __restrict__ bib,
               const float* __restrict__ bhb,
               const float* __restrict__ Wmean, const float* __restrict__ bmean)
{
    extern __shared__ float csm[];
    float* sW   = csm;            // [300*100]
    float* srow = csm + 30000;    // [CBJ][300]

    const int j0 = blockIdx.x * CBJ;
    const int tid = threadIdx.x;

    for (int i = tid; i < 30000; i += 256) sW[i] = Wmean[i];
    for (int i = tid; i < CBJ * 300; i += 256) {
        const int jj = i / 300, d = i % 300, j = j0 + jj;
        float v = 0.f;
        if (j < 1800) v = (j < 900) ? Wf[j * 300 + d] : Wb[(j - 900) * 300 + d];
        srow[i] = v;
    }
    __syncthreads();

    for (int idx = tid; idx < CBJ * KN_PAD; idx += 256) {
        const int jj = idx / KN_PAD, k = idx % KN_PAD, j = j0 + jj;
        if (j >= 1800) continue;
        float s = 0.f;
        if (k < 100) {
            const float* wr = srow + jj * 300;
#pragma unroll 4
            for (int d = 0; d < 300; ++d) s = fmaf(wr[d], sW[d * 100 + k], s);
        }
        g_Wc_h[j * KN_PAD + k] = __float2half(s);
    }
    if (tid < CBJ) {
        const int j = j0 + tid;
        if (j < 1800) {
            const int fwd = (j < 900), jj2 = fwd ? j : j - 900;
            const float* bih = fwd ? bif : bib;
            const float* bhh = fwd ? bhf : bhb;
            const float* wr = srow + tid * 300;
            float s = bih[jj2];
            for (int d = 0; d < 300; ++d) s = fmaf(wr[d], bmean[d], s);
            if (jj2 < 600) s += bhh[jj2];
            g_c[j] = s;
        }
    }
}

// ---------------- GRU gates: read fp16 U, write fp16 hidden ----------------
__device__ __forceinline__ float4 h4_to_f4(const __half* p) {
    uint2 v = *(const uint2*)p;
    __half2 h0 = *reinterpret_cast<__half2*>(&v.x);
    __half2 h1 = *reinterpret_cast<__half2*>(&v.y);
    float2 f0 = __half22float2(h0), f1 = __half22float2(h1);
    return make_float4(f0.x, f0.y, f1.x, f1.y);
}
__device__ __forceinline__ float4 avg4(float4 a, float4 b) {
    return make_float4(0.5f * (a.x + b.x), 0.5f * (a.y + b.y),
                       0.5f * (a.z + b.z), 0.5f * (a.w + b.w));
}
__global__ void __launch_bounds__(160) gates_kernel(const int* __restrict__ tri,
                                                    const float* __restrict__ bhf,
                                                    const float* __restrict__ bhb)
{
    const int bt = blockIdx.x;
    const int b = bt >> 9;
    const int h = tri[bt * 3 + 0];
    const int t = tri[bt * 3 + 2];
    const __half* uh = g_U_h + (size_t)(b * NNODE + h) * 1800;
    const __half* ut = g_U_h + (size_t)(b * NNODE + t) * 1800;
    __half* out = g_hidden_h + (size_t)bt * 600;

    const int tid = threadIdx.x;
    int grp, j;
    if (tid < 75)                    { grp = 0; j = tid; }
    else if (tid >= 80 && tid < 155) { grp = 1; j = tid - 80; }
    else return;

    const int base = grp * 900 + 4 * j;          // half index
    const float* bh = grp ? bhb : bhf;
    const float4 r4 = avg4(h4_to_f4(uh + base),       h4_to_f4(ut + base));
    const float4 z4 = avg4(h4_to_f4(uh + base + 300), h4_to_f4(ut + base + 300));
    const float4 n4 = avg4(h4_to_f4(uh + base + 600), h4_to_f4(ut + base + 600));
    const float4 bb = ((const float4*)(bh + 600))[j];

    float4 o;
    o.x = (1.f - fsigmoid(z4.x)) * ftanh(n4.x + fsigmoid(r4.x) * bb.x);
    o.y = (1.f - fsigmoid(z4.y)) * ftanh(n4.y + fsigmoid(r4.y) * bb.y);
    o.z = (1.f - fsigmoid(z4.z)) * ftanh(n4.z + fsigmoid(r4.z) * bb.z);
    o.w = (1.f - fsigmoid(z4.w)) * ftanh(n4.w + fsigmoid(r4.w) * bb.w);

    __half2 h0 = __floats2half2_rn(o.x, o.y);
    __half2 h1 = __floats2half2_rn(o.z, o.w);
    uint2 v;
    v.x = *reinterpret_cast<uint32_t*>(&h0);
    v.y = *reinterpret_cast<uint32_t*>(&h1);
    *(uint2*)(out + grp * 300 + 4 * j) = v;
}

// ---------------- single-pass softmax over t per (b,l) + alpha[b,t] = sum_l ----------------
__global__ void __launch_bounds__(512) softmax_alpha_kernel()
{
    const int b = blockIdx.x;
    const __half* S = g_scores_h + (size_t)b * NLQ * NT;
    __shared__ float part[16][NT];               // 32 KB

    const int tid = threadIdx.x;
    const int w = tid >> 5, lane = tid & 31;

    float pacc[16];
#pragma unroll
    for (int q = 0; q < 16; ++q) pacc[q] = 0.f;

    for (int l = w; l < NLQ; l += 16) {
        const __half2* row2 = (const __half2*)(S + (size_t)l * NT);
        float v[16], m = -1e30f;
#pragma unroll
        for (int q = 0; q < 8; ++q) {
            float2 f = __half22float2(row2[lane + 32 * q]);
            v[2 * q] = f.x; v[2 * q + 1] = f.y;
            m = fmaxf(m, fmaxf(f.x, f.y));
        }
#pragma unroll
        for (int o = 16; o; o >>= 1) m = fmaxf(m, __shfl_xor_sync(0xffffffffu, m, o));
        float e[16], s = 0.f;
#pragma unroll
        for (int q = 0; q < 16; ++q) { e[q] = fexp2(LOG2E * (v[q] - m)); s += e[q]; }
#pragma unroll
        for (int o = 16; o; o >>= 1) s += __shfl_xor_sync(0xffffffffu, s, o);
        const float rinv = frcp(s);
#pragma unroll
        for (int q = 0; q < 16; ++q) pacc[q] += e[q] * rinv;
    }
#pragma unroll
    for (int q = 0; q < 8; ++q) {
        const int c = 2 * (lane + 32 * q);
        part[w][c]     = pacc[2 * q];
        part[w][c + 1] = pacc[2 * q + 1];
    }
    __syncthreads();

    float s = 0.f;
#pragma unroll
    for (int w2 = 0; w2 < 16; ++w2) s += part[w2][tid];
    g_alpha[b * NT + tid] = s;
}

// ---------------- rep = alpha @ hid_ ; layernorm ----------------
__global__ void __launch_bounds__(320) rep_ln_kernel(const float* __restrict__ gamma,
                                                     const float* __restrict__ beta,
                                                     float* __restrict__ out)
{
    const int b = blockIdx.x;
    __shared__ float sal[NT];
    __shared__ float red[2][10];
    const int tid = threadIdx.x;

    for (int t = tid; t < NT; t += 320) sal[t] = g_alpha[b * NT + t];
    __syncthreads();

    float acc = 0.f;
    const __half* H = g_hid_h + (size_t)b * NT * KH_PAD;
    if (tid < D_HID) {
        for (int t = 0; t < NT; ++t)
            acc = fmaf(sal[t], __half2float(H[(size_t)t * KH_PAD + tid]), acc);
    }
    float v1 = (tid < D_HID) ? acc : 0.f;
    float v2 = (tid < D_HID) ? acc * acc : 0.f;
#pragma unroll
    for (int o = 16; o; o >>= 1) {
        v1 += __shfl_xor_sync(0xffffffffu, v1, o);
        v2 += __shfl_xor_sync(0xffffffffu, v2, o);
    }
    const int wid = tid >> 5, lane = tid & 31;
    if (lane == 0) { red[0][wid] = v1; red[1][wid] = v2; }
    __syncthreads();
    if (tid == 0) {
        float s1 = 0.f, s2 = 0.f;
        for (int w = 0; w < 10; ++w) { s1 += red[0][w]; s2 += red[1][w]; }
        red[0][0] = s1 / (float)D_HID;
        red[1][0] = s2 / (float)D_HID;
    }
    __syncthreads();
    if (tid < D_HID) {
        float mu = red[0][0];
        float var = red[1][0] - mu * mu;
        out[b * D_HID + tid] = (acc - mu) * rsqrtf(var + 1e-5f) * gamma[tid] + beta[tid];
    }
}

__global__ void zero_tail_kernel(float* __restrict__ out, long start, long end)
{
    long i = start + (long)blockIdx.x * blockDim.x + threadIdx.x;
    if (i < end) out[i] = 0.f;
}

// ---------------- launch ----------------
extern "C" void kernel_launch(void* const* d_in, const int* in_sizes, int n_in,
                              void* d_out, int out_size)
{
    const int o = (in_sizes[3] == 1) ? 1 : 0;

    const float* nodes  = (const float*)d_in[0];
    const float* ctx    = (const float*)d_in[1];
    const int*   tri    = (const int*)d_in[2];
    const float* W_mean = (const float*)d_in[3 + o];
    const float* b_mean = (const float*)d_in[4 + o];
    const float* W_ih_f = (const float*)d_in[5 + o];
    const float* b_ih_f = (const float*)d_in[6 + o];
    const float* b_hh_f = (const float*)d_in[7 + o];
    const float* W_ih_b = (const float*)d_in[8 + o];
    const float* b_ih_b = (const float*)d_in[9 + o];
    const float* b_hh_b = (const float*)d_in[10 + o];
    const float* W_out  = (const float*)d_in[11 + o];
    const float* b_out  = (const float*)d_in[12 + o];
    const float* W_node = (const float*)d_in[13 + o];
    const float* b_node = (const float*)d_in[14 + o];
    const float* gamma  = (const float*)d_in[15 + o];
    const float* beta   = (const float*)d_in[16 + o];
    float* out = (float*)d_out;

    __half *pNodesH, *pCtxH, *pWcH, *pWnodeH, *pWoutH, *pUH, *pHiddenH, *pHidH, *pScoresH;
    float* pC;
    cudaGetSymbolAddress((void**)&pNodesH,  g_nodes_h);
    cudaGetSymbolAddress((void**)&pCtxH,    g_ctx_h);
    cudaGetSymbolAddress((void**)&pWcH,     g_Wc_h);
    cudaGetSymbolAddress((void**)&pWnodeH,  g_Wnode_h);
    cudaGetSymbolAddress((void**)&pWoutH,   g_Wout_h);
    cudaGetSymbolAddress((void**)&pC,       g_c);
    cudaGetSymbolAddress((void**)&pUH,      g_U_h);
    cudaGetSymbolAddress((void**)&pHiddenH, g_hidden_h);
    cudaGetSymbolAddress((void**)&pHidH,    g_hid_h);
    cudaGetSymbolAddress((void**)&pScoresH, g_scores_h);

    cudaFuncSetAttribute(combine_kernel, cudaFuncAttributeMaxDynamicSharedMemorySize, COMBINE_SMEM);
    cudaFuncSetAttribute(gemm_f16<true>,  cudaFuncAttributeMaxDynamicSharedMemorySize, GEMM_SMEM_BYTES);
    cudaFuncSetAttribute(gemm_f16<false>, cudaFuncAttributeMaxDynamicSharedMemorySize, GEMM_SMEM_BYTES);

    // 0. fp16 conversions (padded)
    convert_pad<<<4096, 256>>>(nodes,  pNodesH, ROWS_BN, D_NODE, KN_PAD);
    convert_pad<<<8192, 256>>>(ctx,    pCtxH,   NB * NLQ, D_HID, KH_PAD);
    convert_pad<<<132,  256>>>(W_node, pWnodeH, D_HID, D_NODE, KN_PAD);
    convert_pad<<<704,  256>>>(W_out,  pWoutH,  D_HID, 600, 600);

    // 1. combined weights/biases
    combine_kernel<<<(1800 + CBJ - 1) / CBJ, 256, COMBINE_SMEM>>>(
        W_ih_f, b_ih_f, b_hh_f, W_ih_b, b_ih_b, b_hh_b, W_mean, b_mean);

    // 2. U[32768,1800] = nodes @ Wc^T + c   (fp16 out)
    {
        dim3 grid((1800 + BN - 1) / BN, ROWS_BN / BM, 1);
        gemm_f16<true><<<grid, 256, GEMM_SMEM_BYTES>>>(pNodesH, 0, pWcH, 0, pUH, 0,
                                                       ROWS_BN, 1800, 1800, KN_PAD, pC, 0);
    }
    // 3. node_feature[32768,300] = nodes @ W_node^T + b_node   (fp32 out, final)
    {
        dim3 grid((D_HID + BN - 1) / BN, ROWS_BN / BM, 1);
        gemm_f16<false><<<grid, 256, GEMM_SMEM_BYTES>>>(pNodesH, 0, pWnodeH, 0, out + OUT_PATH, 0,
                                                        ROWS_BN, D_HID, D_HID, KN_PAD, b_node, 0);
    }
    // 4. GRU gates -> hidden[65536,600] fp16
    gates_kernel<<<ROWS_BT, 160>>>(tri, b_hh_f, b_hh_b);

    // 5. hid_[65536,304] = tanh(hidden @ W_out^T + b_out)   (fp16 out, padded)
    {
        dim3 grid((KH_PAD + BN - 1) / BN, ROWS_BT / BM, 1);
        gemm_f16<true><<<grid, 256, GEMM_SMEM_BYTES>>>(pHiddenH, 0, pWoutH, 0, pHidH, 0,
                                                       ROWS_BT, D_HID, KH_PAD, 600, b_out, 1);
    }
    // 6. scores[b,256,512] = ctx[b] @ hid_[b]^T   (fp16 out)
    {
        dim3 grid(NT / BN, NLQ / BM, NB);
        gemm_f16<true><<<grid, 256, GEMM_SMEM_BYTES>>>(pCtxH, (long)NLQ * KH_PAD,
                                                       pHidH, (long)NT * KH_PAD,
                                                       pScoresH, (long)NLQ * NT,
                                                       NLQ, NT, NT, KH_PAD, nullptr, 0);
    }
    // 7. single-pass softmax/alpha
    softmax_alpha_kernel<<<NB, 512>>>();
    // 8. rep + layernorm
    rep_ln_kernel<<<NB, 320>>>(gamma, beta, out);
    // 9. node_mask zeros
    {
        long start = OUT_TAIL_START;
        long end = (long)out_size;
        if (end > start) {
            long n = end - start;
            int blocks = (int)((n + 255) / 256);
            zero_tail_kernel<<<blocks, 256>>>(out, start, end);
        }
    }
}

// round 8
// speedup vs baseline: 1.4948x; 1.0409x over previous
#include <cuda_runtime.h>
#include <cuda_fp16.h>
#include <math.h>
#include <stdint.h>

// ---------------- problem constants ----------------
#define D_NODE 100
#define D_HID  300
#define NB     128
#define NT     512
#define NNODE  256
#define NLQ    256
#define ROWS_BT (NB*NT)     // 65536
#define ROWS_BN (NB*NNODE)  // 32768

#define KN_PAD 112          // 100 -> 112
#define KH_PAD 304          // 300 -> 304
#define HPAD   608          // hidden padded: [fwd 304 | bwd 304]
#define NCOLS  1824         // reordered gate cols: 2 dirs x 38 groups x 24

#define OUT_PATH   (NB*D_HID)
#define OUT_NODEF  ((long)ROWS_BN*D_HID)
#define OUT_TAIL_START (OUT_PATH + OUT_NODEF)

// ---------------- device scratch ----------------
__device__ __half g_nodes_h[(size_t)ROWS_BN * KN_PAD];
__device__ __half g_ctx_h[(size_t)NB * NLQ * KH_PAD];
__device__ __half g_T_h[(size_t)ROWS_BT * KN_PAD];        // averaged triple node vecs
__device__ __half g_Wc_h[NCOLS * KN_PAD];                 // reordered combined weights
__device__ float  g_c_r[NCOLS];                           // reordered combined bias
__device__ float  g_bhn[HPAD];                            // n-gate b_hh, [d*304 + j]
__device__ __half g_Wnode_h[300 * KN_PAD];
__device__ __half g_Wout_h[300 * HPAD];                   // K-padded to 608
__device__ __half g_hidden_h[(size_t)ROWS_BT * HPAD];
__device__ __half g_hid_h[(size_t)ROWS_BT * KH_PAD];
__device__ __half g_scores_h[(size_t)NB * NLQ * NT];
__device__ float  g_alpha[NB * NT];

// ---------------- PTX helpers ----------------
__device__ __forceinline__ uint32_t smem_to_u32(const void* p) {
    uint32_t a;
    asm("{ .reg .u64 t; cvta.to.shared.u64 t, %1; cvt.u32.u64 %0, t; }" : "=r"(a) : "l"(p));
    return a;
}
__device__ __forceinline__ void mma_f16(float* d, const uint32_t* a, const uint32_t* b) {
    asm volatile(
        "mma.sync.aligned.m16n8k16.row.col.f32.f16.f16.f32 "
        "{%0,%1,%2,%3}, {%4,%5,%6,%7}, {%8,%9}, {%0,%1,%2,%3};"
        : "+f"(d[0]), "+f"(d[1]), "+f"(d[2]), "+f"(d[3])
        : "r"(a[0]), "r"(a[1]), "r"(a[2]), "r"(a[3]), "r"(b[0]), "r"(b[1]));
}
__device__ __forceinline__ void cp_async16(uint32_t dst, const void* src, int src_size) {
    asm volatile("cp.async.cg.shared.global [%0], [%1], 16, %2;"
        :: "r"(dst), "l"(src), "r"(src_size) : "memory");
}
#define CP_COMMIT() asm volatile("cp.async.commit_group;" ::: "memory")
#define CP_WAIT(n)  asm volatile("cp.async.wait_group %0;" :: "n"(n) : "memory")

__device__ __forceinline__ float fexp2(float x) {
    float y; asm("ex2.approx.f32 %0, %1;" : "=f"(y) : "f"(x)); return y;
}
__device__ __forceinline__ float frcp(float x) {
    float y; asm("rcp.approx.f32 %0, %1;" : "=f"(y) : "f"(x)); return y;
}
#define LOG2E 1.4426950408889634f
__device__ __forceinline__ float fsigmoid(float x) { return frcp(1.f + fexp2(-LOG2E * x)); }
__device__ __forceinline__ float ftanh(float x)    { return 2.f * frcp(1.f + fexp2(-2.f * LOG2E * x)) - 1.f; }

// ================= generic fp16 mma GEMM (unchanged R5 core, 2-stage) =================
#define BM 128
#define BN 128
#define ASTR 40

template <bool OUT_HALF>
__global__ void __launch_bounds__(256, 2)
gemm_f16(const __half* __restrict__ A, long aBatch,
         const __half* __restrict__ W, long wBatch,
         void* __restrict__ Cv, long cBatch,
         int M, int N, int Npad, int K,
         const float* __restrict__ bias, int act_tanh)
{
    __shared__ __half sA[2][BM * ASTR];
    __shared__ __half sB[2][BN * ASTR];

    const int bz = blockIdx.z;
    A += (long)bz * aBatch; W += (long)bz * wBatch;

    const int tid  = threadIdx.x;
    const int warp = tid >> 5, lane = tid & 31;
    const int wm = warp & 3, wn = warp >> 2;
    const int g = lane >> 2, t = lane & 3;

    const int m0 = blockIdx.y * BM;
    const int n0 = blockIdx.x * BN;
    const int CH = (K + 31) >> 5;

    const uint32_t sA32 = smem_to_u32(sA);
    const uint32_t sB32 = smem_to_u32(sB);

    float acc[2][8][4];
#pragma unroll
    for (int i = 0; i < 2; ++i)
#pragma unroll
        for (int j = 0; j < 8; ++j)
#pragma unroll
            for (int q = 0; q < 4; ++q) acc[i][j][q] = 0.f;

    auto issue = [&](int c) {
        const int s = c & 1;
        const int kb = c << 5;
        const uint32_t aB = sA32 + (uint32_t)s * (BM * ASTR * 2);
        const uint32_t bB = sB32 + (uint32_t)s * (BN * ASTR * 2);
#pragma unroll
        for (int i = 0; i < 2; ++i) {
            const int seg = tid + i * 256;
            const int row = seg >> 2, q = seg & 3;
            const int k = kb + q * 8;
            const int va = (k + 8 <= K);
            cp_async16(aB + (uint32_t)(row * (ASTR * 2) + q * 16),
                       va ? (const void*)(A + (long)(m0 + row) * K + k) : (const void*)A,
                       va ? 16 : 0);
            const int vb = va && (n0 + row < N);
            cp_async16(bB + (uint32_t)(row * (ASTR * 2) + q * 16),
                       vb ? (const void*)(W + (long)(n0 + row) * K + k) : (const void*)W,
                       vb ? 16 : 0);
        }
        CP_COMMIT();
    };

    issue(0);
    for (int c = 0; c < CH; ++c) {
        if (c + 1 < CH) { issue(c + 1); CP_WAIT(1); }
        else            { CP_WAIT(0); }
        __syncthreads();

        const __half* a_ = sA[c & 1];
        const __half* b_ = sB[c & 1];

#pragma unroll
        for (int kk = 0; kk < 2; ++kk) {
            const int col = kk * 16 + 2 * t;
            uint32_t af[2][4], bf[8][2];
#pragma unroll
            for (int tm = 0; tm < 2; ++tm) {
                const int r = wm * 32 + tm * 16 + g;
                af[tm][0] = *(const uint32_t*)(a_ + r * ASTR + col);
                af[tm][1] = *(const uint32_t*)(a_ + (r + 8) * ASTR + col);
                af[tm][2] = *(const uint32_t*)(a_ + r * ASTR + col + 8);
                af[tm][3] = *(const uint32_t*)(a_ + (r + 8) * ASTR + col + 8);
            }
#pragma unroll
            for (int tn = 0; tn < 8; ++tn) {
                const int n = wn * 64 + tn * 8 + g;
                bf[tn][0] = *(const uint32_t*)(b_ + n * ASTR + col);
                bf[tn][1] = *(const uint32_t*)(b_ + n * ASTR + col + 8);
            }
#pragma unroll
            for (int tm = 0; tm < 2; ++tm)
#pragma unroll
                for (int tn = 0; tn < 8; ++tn)
                    mma_f16(acc[tm][tn], af[tm], bf[tn]);
        }
        __syncthreads();
    }

#pragma unroll
    for (int tm = 0; tm < 2; ++tm) {
        const int row = m0 + wm * 32 + tm * 16 + g;
#pragma unroll
        for (int tn = 0; tn < 8; ++tn) {
            const int n = n0 + wn * 64 + tn * 8 + 2 * t;
            if (OUT_HALF ? (n < Npad) : (n < N)) {
                float v0 = 0.f, v1 = 0.f, v2 = 0.f, v3 = 0.f;
                if (n < N) {
                    float b0 = 0.f, b1 = 0.f;
                    if (bias) { b0 = bias[n]; b1 = bias[n + 1]; }
                    v0 = acc[tm][tn][0] + b0;
                    v1 = acc[tm][tn][1] + b1;
                    v2 = acc[tm][tn][2] + b0;
                    v3 = acc[tm][tn][3] + b1;
                    if (act_tanh) { v0 = ftanh(v0); v1 = ftanh(v1); v2 = ftanh(v2); v3 = ftanh(v3); }
                }
                if constexpr (OUT_HALF) {
                    __half* C = (__half*)Cv + (long)bz * cBatch;
                    *(__half2*)(C + (size_t)row * Npad + n)       = __floats2half2_rn(v0, v1);
                    *(__half2*)(C + (size_t)(row + 8) * Npad + n) = __floats2half2_rn(v2, v3);
                } else {
                    float* C = (float*)Cv + (long)bz * cBatch;
                    *(float2*)(C + (size_t)row * N + n)       = make_float2(v0, v1);
                    *(float2*)(C + (size_t)(row + 8) * N + n) = make_float2(v2, v3);
                }
            }
        }
    }
}

// ================= gi-GEMM with fused GRU gates epilogue =================
// hidden[bt][d*304+j] = (1-sig(z))*tanh(n + sig(r)*bhn[d*304+j]),
// where [r,z,n](bt, d, j) = T[bt] . Wc_col + c_r, Wc cols ordered in
// 24-col groups: [r_{8j..}, z_{8j..}, n_{8j..}] per group, 38 groups/dir.
#define GSTR 120                                // smem row stride (halves); conflict-free
#define GA_HALVES (128 * GSTR)
#define GB_HALVES (96 * GSTR)
#define GATES_SMEM ((GA_HALVES + 2 * GB_HALVES) * 2)   // 76800 B
#define GNT 19                                  // 1824 / 96 n-tiles

__global__ void __launch_bounds__(256, 2) gemm_gates()
{
    extern __shared__ __half gsm[];
    __half* sA = gsm;
    __half* sB = gsm + GA_HALVES;

    const int tid  = threadIdx.x;
    const int warp = tid >> 5, lane = tid & 31;
    const int wm = warp & 3, wn = warp >> 2;     // 4 x 2
    const int g = lane >> 2, t = lane & 3;
    const int m0 = blockIdx.x * 128;

    const uint32_t sA32 = smem_to_u32(sA);
    const uint32_t sB32 = smem_to_u32(sB);

    auto issueB = [&](int nt) {
        const uint32_t bB = sB32 + (uint32_t)((nt & 1) * GB_HALVES * 2);
#pragma unroll
        for (int i = 0; i < 6; ++i) {
            const int seg = tid + i * 256;       // 96*14 = 1344
            if (seg < 1344) {
                const int row = seg / 14, q = seg % 14;
                cp_async16(bB + (uint32_t)(row * (GSTR * 2) + q * 16),
                           g_Wc_h + (size_t)(nt * 96 + row) * KN_PAD + q * 8, 16);
            }
        }
        CP_COMMIT();
    };

    // prologue: A + B0 in group0, B1 in group1
#pragma unroll
    for (int i = 0; i < 7; ++i) {
        const int seg = tid + i * 256;           // 128*14 = 1792
        const int row = seg / 14, q = seg % 14;
        cp_async16(sA32 + (uint32_t)(row * (GSTR * 2) + q * 16),
                   g_T_h + (size_t)(m0 + row) * KN_PAD + q * 8, 16);
    }
    {
        const uint32_t bB = sB32;
#pragma unroll
        for (int i = 0; i < 6; ++i) {
            const int seg = tid + i * 256;
            if (seg < 1344) {
                const int row = seg / 14, q = seg % 14;
                cp_async16(bB + (uint32_t)(row * (GSTR * 2) + q * 16),
                           g_Wc_h + (size_t)row * KN_PAD + q * 8, 16);
            }
        }
        CP_COMMIT();
    }
    issueB(1);

#pragma unroll 1
    for (int nt = 0; nt < GNT; ++nt) {
        CP_WAIT(1);
        __syncthreads();

        const __half* a_ = sA;
        const __half* b_ = sB + (nt & 1) * GB_HALVES;

        float acc[2][6][4];
#pragma unroll
        for (int i = 0; i < 2; ++i)
#pragma unroll
            for (int j = 0; j < 6; ++j)
#pragma unroll
                for (int q = 0; q < 4; ++q) acc[i][j][q] = 0.f;

#pragma unroll
        for (int kk = 0; kk < 7; ++kk) {         // 112 / 16
            const int col = kk * 16 + 2 * t;
            uint32_t af[2][4], bf[6][2];
#pragma unroll
            for (int tm = 0; tm < 2; ++tm) {
                const int r = wm * 32 + tm * 16 + g;
                af[tm][0] = *(const uint32_t*)(a_ + r * GSTR + col);
                af[tm][1] = *(const uint32_t*)(a_ + (r + 8) * GSTR + col);
                af[tm][2] = *(const uint32_t*)(a_ + r * GSTR + col + 8);
                af[tm][3] = *(const uint32_t*)(a_ + (r + 8) * GSTR + col + 8);
            }
#pragma unroll
            for (int tn = 0; tn < 6; ++tn) {
                const int n = wn * 48 + tn * 8 + g;
                bf[tn][0] = *(const uint32_t*)(b_ + n * GSTR + col);
                bf[tn][1] = *(const uint32_t*)(b_ + n * GSTR + col + 8);
            }
#pragma unroll
            for (int tm = 0; tm < 2; ++tm)
#pragma unroll
                for (int tn = 0; tn < 6; ++tn)
                    mma_f16(acc[tm][tn], af[tm], bf[tn]);
        }
        __syncthreads();
        // prefetch next B while doing the gate epilogue
        if (nt + 2 < GNT) issueB(nt + 2);
        else              CP_COMMIT();

        // ---- fused GRU gate epilogue ----
        const int n0 = nt * 96;
#pragma unroll
        for (int G = 0; G < 2; ++G) {
            const int colbase = n0 + wn * 48 + G * 24;    // multiple of 24
            const int d = (colbase >= 912);
            const int grp = (colbase - d * 912) / 24;
            const int j0 = grp * 8 + 2 * t;               // even
            const float bh0 = g_bhn[d * 304 + j0];
            const float bh1 = g_bhn[d * 304 + j0 + 1];
            const float cr0 = g_c_r[colbase + 2 * t];
            const float cr1 = g_c_r[colbase + 2 * t + 1];
            const float cz0 = g_c_r[colbase + 8 + 2 * t];
            const float cz1 = g_c_r[colbase + 8 + 2 * t + 1];
            const float cn0 = g_c_r[colbase + 16 + 2 * t];
            const float cn1 = g_c_r[colbase + 16 + 2 * t + 1];
            const bool valid = (j0 < 300);
#pragma unroll
            for (int tm = 0; tm < 2; ++tm) {
#pragma unroll
                for (int rr = 0; rr < 2; ++rr) {
                    const int bt = m0 + wm * 32 + tm * 16 + g + rr * 8;
                    float h0 = 0.f, h1 = 0.f;
                    if (valid) {
                        const int q0 = rr * 2;
                        const float r0 = fsigmoid(acc[tm][3 * G + 0][q0]     + cr0);
                        const float r1 = fsigmoid(acc[tm][3 * G + 0][q0 + 1] + cr1);
                        const float z0 = fsigmoid(acc[tm][3 * G + 1][q0]     + cz0);
                        const float z1 = fsigmoid(acc[tm][3 * G + 1][q0 + 1] + cz1);
                        const float n0_ = acc[tm][3 * G + 2][q0]     + cn0;
                        const float n1_ = acc[tm][3 * G + 2][q0 + 1] + cn1;
                        h0 = (1.f - z0) * ftanh(n0_ + r0 * bh0);
                        h1 = (1.f - z1) * ftanh(n1_ + r1 * bh1);
                    }
                    *(__half2*)(g_hidden_h + (size_t)bt * HPAD + d * 304 + j0) =
                        __floats2half2_rn(h0, h1);
                }
            }
        }
        __syncthreads();   // epilogue done before buffer (nt&1) overwritten? issued above into (nt)&1 — reads were from b_ in compute (already sync'd); this sync orders next iteration's wait.
    }
}

// ---------------- fp32 -> fp16 convert with row padding ----------------
__global__ void convert_pad(const float* __restrict__ src, __half* __restrict__ dst,
                            int rows, int K, int Kpad)
{
    const int total = rows * Kpad;
    for (int i = blockIdx.x * blockDim.x + threadIdx.x; i < total; i += gridDim.x * blockDim.x) {
        const int r = i / Kpad, k = i - r * Kpad;
        dst[i] = __float2half((k < K) ? src[(size_t)r * K + k] : 0.f);
    }
}

// ---------------- W_out K-pad convert: [300][600] -> [300][608] ----------------
__global__ void convert_wout(const float* __restrict__ W, __half* __restrict__ dst)
{
    const int i = blockIdx.x * blockDim.x + threadIdx.x;
    if (i >= 300 * HPAD) return;
    const int n = i / HPAD, k = i % HPAD;
    float v = 0.f;
    if (k < 300)                  v = W[n * 600 + k];
    else if (k >= 304 && k < 604) v = W[n * 600 + (k - 4)];
    dst[i] = __float2half(v);
}

// ---------------- weight combine -> reordered Wc_h / c_r / bhn ----------------
#define CBJ 16
#define COMBINE_SMEM ((30000 + CBJ * 300) * 4)

__global__ void __launch_bounds__(256)
combine_kernel(const float* __restrict__ Wf, const float* __restrict__ bif,
               const float* __restrict__ bhf,
               const float* __restrict__ Wb, const float* __restrict__ bib,
               const float* __restrict__ bhb,
               const float* __restrict__ Wmean, const float* __restrict__ bmean)
{
    extern __shared__ float csm[];
    float* sW   = csm;            // [300*100]
    float* srow = csm + 30000;    // [CBJ][300]

    const int j0 = blockIdx.x * CBJ;             // 1824 / 16 = 114 blocks
    const int tid = threadIdx.x;

    for (int i = tid; i < 30000; i += 256) sW[i] = Wmean[i];
    for (int i = tid; i < CBJ * 300; i += 256) {
        const int jj = i / 300, dcol = i % 300;
        const int cnew = j0 + jj;
        const int d = (cnew >= 912);
        const int rem = cnew - d * 912;
        const int grp = rem / 24, gate = (rem % 24) >> 3, pos = rem & 7;
        const int h = grp * 8 + pos;
        float v = 0.f;
        if (h < 300) {
            const int src = gate * 300 + h;
            v = d ? Wb[src * 300 + dcol] : Wf[src * 300 + dcol];
        }
        srow[i] = v;
    }
    __syncthreads();

    for (int idx = tid; idx < CBJ * KN_PAD; idx += 256) {
        const int jj = idx / KN_PAD, k = idx % KN_PAD;
        const int cnew = j0 + jj;
        float s = 0.f;
        if (k < 100) {
            const float* wr = srow + jj * 300;
#pragma unroll 4
            for (int dd = 0; dd < 300; ++dd) s = fmaf(wr[dd], sW[dd * 100 + k], s);
        }
        g_Wc_h[(size_t)cnew * KN_PAD + k] = __float2half(s);
    }
    if (tid < CBJ) {
        const int cnew = j0 + tid;
        const int d = (cnew >= 912);
        const int rem = cnew - d * 912;
        const int grp = rem / 24, gate = (rem % 24) >> 3, pos = rem & 7;
        const int h = grp * 8 + pos;
        float s = 0.f;
        if (h < 300) {
            const int src = gate * 300 + h;
            const float* bih = d ? bib : bif;
            const float* bhh = d ? bhb : bhf;
            s = bih[src];
            const float* wr = srow + tid * 300;
            for (int dd = 0; dd < 300; ++dd) s = fmaf(wr[dd], bmean[dd], s);
            if (gate < 2) s += bhh[src];
            if (gate == 2) g_bhn[d * 304 + h] = bhh[600 + h];
        } else {
            if (gate == 2) g_bhn[d * 304 + h] = 0.f;
        }
        g_c_r[cnew] = s;
    }
}

// ---------------- per-triple averaged node vectors ----------------
__global__ void __launch_bounds__(224) tri_avg(const int* __restrict__ tri)
{
    const int r = threadIdx.x / 28, c = threadIdx.x % 28;   // 8 rows x 28 uint2-chunks
    const int bt = blockIdx.x * 8 + r;
    const int b = bt >> 9;
    const int hN = tri[bt * 3 + 0];
    const int tN = tri[bt * 3 + 2];
    const uint2 vh = ((const uint2*)(g_nodes_h + (size_t)(b * NNODE + hN) * KN_PAD))[c];
    const uint2 vt = ((const uint2*)(g_nodes_h + (size_t)(b * NNODE + tN) * KN_PAD))[c];
    const float2 hx = __half22float2(*(const __half2*)&vh.x);
    const float2 hy = __half22float2(*(const __half2*)&vh.y);
    const float2 tx = __half22float2(*(const __half2*)&vt.x);
    const float2 ty = __half22float2(*(const __half2*)&vt.y);
    __half2 o0 = __floats2half2_rn(0.5f * (hx.x + tx.x), 0.5f * (hx.y + tx.y));
    __half2 o1 = __floats2half2_rn(0.5f * (hy.x + ty.x), 0.5f * (hy.y + ty.y));
    uint2 o;
    o.x = *(uint32_t*)&o0;
    o.y = *(uint32_t*)&o1;
    ((uint2*)(g_T_h + (size_t)bt * KN_PAD))[c] = o;
}

// ---------------- single-pass softmax over t per (b,l) + alpha ----------------
__global__ void __launch_bounds__(512) softmax_alpha_kernel()
{
    const int b = blockIdx.x;
    const __half* S = g_scores_h + (size_t)b * NLQ * NT;
    __shared__ float part[16][NT];

    const int tid = threadIdx.x;
    const int w = tid >> 5, lane = tid & 31;

    float pacc[16];
#pragma unroll
    for (int q = 0; q < 16; ++q) pacc[q] = 0.f;

    for (int l = w; l < NLQ; l += 16) {
        const __half2* row2 = (const __half2*)(S + (size_t)l * NT);
        float v[16], m = -1e30f;
#pragma unroll
        for (int q = 0; q < 8; ++q) {
            float2 f = __half22float2(row2[lane + 32 * q]);
            v[2 * q] = f.x; v[2 * q + 1] = f.y;
            m = fmaxf(m, fmaxf(f.x, f.y));
        }
#pragma unroll
        for (int o = 16; o; o >>= 1) m = fmaxf(m, __shfl_xor_sync(0xffffffffu, m, o));
        float e[16], s = 0.f;
#pragma unroll
        for (int q = 0; q < 16; ++q) { e[q] = fexp2(LOG2E * (v[q] - m)); s += e[q]; }
#pragma unroll
        for (int o = 16; o; o >>= 1) s += __shfl_xor_sync(0xffffffffu, s, o);
        const float rinv = frcp(s);
#pragma unroll
        for (int q = 0; q < 16; ++q) pacc[q] += e[q] * rinv;
    }
#pragma unroll
    for (int q = 0; q < 8; ++q) {
        const int c = 2 * (lane + 32 * q);
        part[w][c]     = pacc[2 * q];
        part[w][c + 1] = pacc[2 * q + 1];
    }
    __syncthreads();

    float s = 0.f;
#pragma unroll
    for (int w2 = 0; w2 < 16; ++w2) s += part[w2][tid];
    g_alpha[b * NT + tid] = s;
}

// ---------------- rep = alpha @ hid_ ; layernorm ----------------
__global__ void __launch_bounds__(320) rep_ln_kernel(const float* __restrict__ gamma,
                                                     const float* __restrict__ beta,
                                                     float* __restrict__ out)
{
    const int b = blockIdx.x;
    __shared__ float sal[NT];
    __shared__ float red[2][10];
    const int tid = threadIdx.x;

    for (int t = tid; t < NT; t += 320) sal[t] = g_alpha[b * NT + t];
    __syncthreads();

    float acc = 0.f;
    const __half* H = g_hid_h + (size_t)b * NT * KH_PAD;
    if (tid < D_HID) {
        for (int t = 0; t < NT; ++t)
            acc = fmaf(sal[t], __half2float(H[(size_t)t * KH_PAD + tid]), acc);
    }
    float v1 = (tid < D_HID) ? acc : 0.f;
    float v2 = (tid < D_HID) ? acc * acc : 0.f;
#pragma unroll
    for (int o = 16; o; o >>= 1) {
        v1 += __shfl_xor_sync(0xffffffffu, v1, o);
        v2 += __shfl_xor_sync(0xffffffffu, v2, o);
    }
    const int wid = tid >> 5, lane = tid & 31;
    if (lane == 0) { red[0][wid] = v1; red[1][wid] = v2; }
    __syncthreads();
    if (tid == 0) {
        float s1 = 0.f, s2 = 0.f;
        for (int w = 0; w < 10; ++w) { s1 += red[0][w]; s2 += red[1][w]; }
        red[0][0] = s1 / (float)D_HID;
        red[1][0] = s2 / (float)D_HID;
    }
    __syncthreads();
    if (tid < D_HID) {
        float mu = red[0][0];
        float var = red[1][0] - mu * mu;
        out[b * D_HID + tid] = (acc - mu) * rsqrtf(var + 1e-5f) * gamma[tid] + beta[tid];
    }
}

__global__ void zero_tail_kernel(float* __restrict__ out, long start, long end)
{
    long i = start + (long)blockIdx.x * blockDim.x + threadIdx.x;
    if (i < end) out[i] = 0.f;
}

// ---------------- launch ----------------
extern "C" void kernel_launch(void* const* d_in, const int* in_sizes, int n_in,
                              void* d_out, int out_size)
{
    const int o = (in_sizes[3] == 1) ? 1 : 0;

    const float* nodes  = (const float*)d_in[0];
    const float* ctx    = (const float*)d_in[1];
    const int*   tri    = (const int*)d_in[2];
    const float* W_mean = (const float*)d_in[3 + o];
    const float* b_mean = (const float*)d_in[4 + o];
    const float* W_ih_f = (const float*)d_in[5 + o];
    const float* b_ih_f = (const float*)d_in[6 + o];
    const float* b_hh_f = (const float*)d_in[7 + o];
    const float* W_ih_b = (const float*)d_in[8 + o];
    const float* b_ih_b = (const float*)d_in[9 + o];
    const float* b_hh_b = (const float*)d_in[10 + o];
    const float* W_out  = (const float*)d_in[11 + o];
    const float* b_out  = (const float*)d_in[12 + o];
    const float* W_node = (const float*)d_in[13 + o];
    const float* b_node = (const float*)d_in[14 + o];
    const float* gamma  = (const float*)d_in[15 + o];
    const float* beta   = (const float*)d_in[16 + o];
    float* out = (float*)d_out;

    __half *pNodesH, *pCtxH, *pWnodeH, *pWoutH, *pHiddenH, *pHidH, *pScoresH;
    cudaGetSymbolAddress((void**)&pNodesH,  g_nodes_h);
    cudaGetSymbolAddress((void**)&pCtxH,    g_ctx_h);
    cudaGetSymbolAddress((void**)&pWnodeH,  g_Wnode_h);
    cudaGetSymbolAddress((void**)&pWoutH,   g_Wout_h);
    cudaGetSymbolAddress((void**)&pHiddenH, g_hidden_h);
    cudaGetSymbolAddress((void**)&pHidH,    g_hid_h);
    cudaGetSymbolAddress((void**)&pScoresH, g_scores_h);

    cudaFuncSetAttribute(combine_kernel, cudaFuncAttributeMaxDynamicSharedMemorySize, COMBINE_SMEM);
    cudaFuncSetAttribute(gemm_gates,     cudaFuncAttributeMaxDynamicSharedMemorySize, GATES_SMEM);

    // 0. fp16 conversions (padded)
    convert_pad<<<4096, 256>>>(nodes,  pNodesH, ROWS_BN, D_NODE, KN_PAD);
    convert_pad<<<8192, 256>>>(ctx,    pCtxH,   NB * NLQ, D_HID, KH_PAD);
    convert_pad<<<132,  256>>>(W_node, pWnodeH, D_HID, D_NODE, KN_PAD);
    convert_wout<<<(300 * HPAD + 255) / 256, 256>>>(W_out, pWoutH);

    // 1. combined + reordered weights/biases
    combine_kernel<<<NCOLS / CBJ, 256, COMBINE_SMEM>>>(
        W_ih_f, b_ih_f, b_hh_f, W_ih_b, b_ih_b, b_hh_b, W_mean, b_mean);

    // 2. averaged triple node vectors T[65536,112]
    tri_avg<<<ROWS_BT / 8, 224>>>(tri);

    // 3. gi-GEMM + fused GRU gates -> hidden[65536,608]
    gemm_gates<<<ROWS_BT / 128, 256, GATES_SMEM>>>();

    // 4. node_feature[32768,300] = nodes @ W_node^T + b_node (fp32, final)
    {
        dim3 grid((D_HID + BN - 1) / BN, ROWS_BN / BM, 1);
        gemm_f16<false><<<grid, 256>>>(pNodesH, 0, pWnodeH, 0, out + OUT_PATH, 0,
                                       ROWS_BN, D_HID, D_HID, KN_PAD, b_node, 0);
    }
    // 5. hid_[65536,304] = tanh(hidden @ W_out^T + b_out)
    {
        dim3 grid((KH_PAD + BN - 1) / BN, ROWS_BT / BM, 1);
        gemm_f16<true><<<grid, 256>>>(pHiddenH, 0, pWoutH, 0, pHidH, 0,
                                      ROWS_BT, D_HID, KH_PAD, HPAD, b_out, 1);
    }
    // 6. scores[b,256,512] = ctx[b] @ hid_[b]^T
    {
        dim3 grid(NT / BN, NLQ / BM, NB);
        gemm_f16<true><<<grid, 256>>>(pCtxH, (long)NLQ * KH_PAD,
                                      pHidH, (long)NT * KH_PAD,
                                      pScoresH, (long)NLQ * NT,
                                      NLQ, NT, NT, KH_PAD, nullptr, 0);
    }
    // 7. softmax/alpha
    softmax_alpha_kernel<<<NB, 512>>>();
    // 8. rep + layernorm
    rep_ln_kernel<<<NB, 320>>>(gamma, beta, out);
    // 9. node_mask zeros
    {
        long start = OUT_TAIL_START;
        long end = (long)out_size;
        if (end > start) {
            long n = end - start;
            int blocks = (int)((n + 255) / 256);
            zero_tail_kernel<<<blocks, 256>>>(out, start, end);
        }
    }
}

// round 9
// speedup vs baseline: 1.5287x; 1.0227x over previous
#include <cuda_runtime.h>
#include <cuda_fp16.h>
#include <math.h>
#include <stdint.h>

// ---------------- problem constants ----------------
#define D_NODE 100
#define D_HID  300
#define NB     128
#define NT     512
#define NNODE  256
#define NLQ    256
#define ROWS_BT (NB*NT)     // 65536
#define ROWS_BN (NB*NNODE)  // 32768

#define KN_PAD 112
#define KH_PAD 304
#define HPAD   608          // hidden padded: [fwd 304 | bwd 304]
#define NCOLS  1824         // reordered gate cols

#define OUT_PATH   (NB*D_HID)
#define OUT_NODEF  ((long)ROWS_BN*D_HID)
#define OUT_TAIL_START (OUT_PATH + OUT_NODEF)

// ---------------- device scratch ----------------
__device__ __half g_nodes_h[(size_t)ROWS_BN * KN_PAD];
__device__ __half g_ctx_h[(size_t)NB * NLQ * KH_PAD];
__device__ __half g_T_h[(size_t)ROWS_BT * KN_PAD];
__device__ __half g_Wc_h[NCOLS * KN_PAD];
__device__ float  g_c_r[NCOLS];
__device__ float  g_bhn[HPAD];
__device__ __half g_Wnode_h[300 * KN_PAD];
__device__ __half g_Wout_h[300 * HPAD];
__device__ __half g_hidden_h[(size_t)ROWS_BT * HPAD];
__device__ __half g_hid_h[(size_t)ROWS_BT * KH_PAD];
__device__ float  g_alpha2[NB * 2 * NT];                  // per-(b,lblock) partial alphas

// ---------------- PTX helpers ----------------
__device__ __forceinline__ uint32_t smem_to_u32(const void* p) {
    uint32_t a;
    asm("{ .reg .u64 t; cvta.to.shared.u64 t, %1; cvt.u32.u64 %0, t; }" : "=r"(a) : "l"(p));
    return a;
}
__device__ __forceinline__ void mma_f16(float* d, const uint32_t* a, const uint32_t* b) {
    asm volatile(
        "mma.sync.aligned.m16n8k16.row.col.f32.f16.f16.f32 "
        "{%0,%1,%2,%3}, {%4,%5,%6,%7}, {%8,%9}, {%0,%1,%2,%3};"
        : "+f"(d[0]), "+f"(d[1]), "+f"(d[2]), "+f"(d[3])
        : "r"(a[0]), "r"(a[1]), "r"(a[2]), "r"(a[3]), "r"(b[0]), "r"(b[1]));
}
__device__ __forceinline__ void cp_async16(uint32_t dst, const void* src, int src_size) {
    asm volatile("cp.async.cg.shared.global [%0], [%1], 16, %2;"
        :: "r"(dst), "l"(src), "r"(src_size) : "memory");
}
#define CP_COMMIT() asm volatile("cp.async.commit_group;" ::: "memory")
#define CP_WAIT(n)  asm volatile("cp.async.wait_group %0;" :: "n"(n) : "memory")

__device__ __forceinline__ float fexp2(float x) {
    float y; asm("ex2.approx.f32 %0, %1;" : "=f"(y) : "f"(x)); return y;
}
__device__ __forceinline__ float frcp(float x) {
    float y; asm("rcp.approx.f32 %0, %1;" : "=f"(y) : "f"(x)); return y;
}
#define LOG2E 1.4426950408889634f
__device__ __forceinline__ float fsigmoid(float x) { return frcp(1.f + fexp2(-LOG2E * x)); }
__device__ __forceinline__ float ftanh(float x)    { return 2.f * frcp(1.f + fexp2(-2.f * LOG2E * x)) - 1.f; }

// ================= generic fp16 mma GEMM =================
#define BM 128
#define BN 128
#define ASTR 40

template <bool OUT_HALF>
__global__ void __launch_bounds__(256, 2)
gemm_f16(const __half* __restrict__ A, long aBatch,
         const __half* __restrict__ W, long wBatch,
         void* __restrict__ Cv, long cBatch,
         int M, int N, int Npad, int K,
         const float* __restrict__ bias, int act_tanh)
{
    __shared__ __half sA[2][BM * ASTR];
    __shared__ __half sB[2][BN * ASTR];

    const int bz = blockIdx.z;
    A += (long)bz * aBatch; W += (long)bz * wBatch;

    const int tid  = threadIdx.x;
    const int warp = tid >> 5, lane = tid & 31;
    const int wm = warp & 3, wn = warp >> 2;
    const int g = lane >> 2, t = lane & 3;

    const int m0 = blockIdx.y * BM;
    const int n0 = blockIdx.x * BN;
    const int CH = (K + 31) >> 5;

    const uint32_t sA32 = smem_to_u32(sA);
    const uint32_t sB32 = smem_to_u32(sB);

    float acc[2][8][4];
#pragma unroll
    for (int i = 0; i < 2; ++i)
#pragma unroll
        for (int j = 0; j < 8; ++j)
#pragma unroll
            for (int q = 0; q < 4; ++q) acc[i][j][q] = 0.f;

    auto issue = [&](int c) {
        const int s = c & 1;
        const int kb = c << 5;
        const uint32_t aB = sA32 + (uint32_t)s * (BM * ASTR * 2);
        const uint32_t bB = sB32 + (uint32_t)s * (BN * ASTR * 2);
#pragma unroll
        for (int i = 0; i < 2; ++i) {
            const int seg = tid + i * 256;
            const int row = seg >> 2, q = seg & 3;
            const int k = kb + q * 8;
            const int va = (k + 8 <= K);
            cp_async16(aB + (uint32_t)(row * (ASTR * 2) + q * 16),
                       va ? (const void*)(A + (long)(m0 + row) * K + k) : (const void*)A,
                       va ? 16 : 0);
            const int vb = va && (n0 + row < N);
            cp_async16(bB + (uint32_t)(row * (ASTR * 2) + q * 16),
                       vb ? (const void*)(W + (long)(n0 + row) * K + k) : (const void*)W,
                       vb ? 16 : 0);
        }
        CP_COMMIT();
    };

    issue(0);
    for (int c = 0; c < CH; ++c) {
        if (c + 1 < CH) { issue(c + 1); CP_WAIT(1); }
        else            { CP_WAIT(0); }
        __syncthreads();

        const __half* a_ = sA[c & 1];
        const __half* b_ = sB[c & 1];

#pragma unroll
        for (int kk = 0; kk < 2; ++kk) {
            const int col = kk * 16 + 2 * t;
            uint32_t af[2][4], bf[8][2];
#pragma unroll
            for (int tm = 0; tm < 2; ++tm) {
                const int r = wm * 32 + tm * 16 + g;
                af[tm][0] = *(const uint32_t*)(a_ + r * ASTR + col);
                af[tm][1] = *(const uint32_t*)(a_ + (r + 8) * ASTR + col);
                af[tm][2] = *(const uint32_t*)(a_ + r * ASTR + col + 8);
                af[tm][3] = *(const uint32_t*)(a_ + (r + 8) * ASTR + col + 8);
            }
#pragma unroll
            for (int tn = 0; tn < 8; ++tn) {
                const int n = wn * 64 + tn * 8 + g;
                bf[tn][0] = *(const uint32_t*)(b_ + n * ASTR + col);
                bf[tn][1] = *(const uint32_t*)(b_ + n * ASTR + col + 8);
            }
#pragma unroll
            for (int tm = 0; tm < 2; ++tm)
#pragma unroll
                for (int tn = 0; tn < 8; ++tn)
                    mma_f16(acc[tm][tn], af[tm], bf[tn]);
        }
        __syncthreads();
    }

#pragma unroll
    for (int tm = 0; tm < 2; ++tm) {
        const int row = m0 + wm * 32 + tm * 16 + g;
#pragma unroll
        for (int tn = 0; tn < 8; ++tn) {
            const int n = n0 + wn * 64 + tn * 8 + 2 * t;
            if (OUT_HALF ? (n < Npad) : (n < N)) {
                float v0 = 0.f, v1 = 0.f, v2 = 0.f, v3 = 0.f;
                if (n < N) {
                    float b0 = 0.f, b1 = 0.f;
                    if (bias) { b0 = bias[n]; b1 = bias[n + 1]; }
                    v0 = acc[tm][tn][0] + b0;
                    v1 = acc[tm][tn][1] + b1;
                    v2 = acc[tm][tn][2] + b0;
                    v3 = acc[tm][tn][3] + b1;
                    if (act_tanh) { v0 = ftanh(v0); v1 = ftanh(v1); v2 = ftanh(v2); v3 = ftanh(v3); }
                }
                if constexpr (OUT_HALF) {
                    __half* C = (__half*)Cv + (long)bz * cBatch;
                    *(__half2*)(C + (size_t)row * Npad + n)       = __floats2half2_rn(v0, v1);
                    *(__half2*)(C + (size_t)(row + 8) * Npad + n) = __floats2half2_rn(v2, v3);
                } else {
                    float* C = (float*)Cv + (long)bz * cBatch;
                    *(float2*)(C + (size_t)row * N + n)       = make_float2(v0, v1);
                    *(float2*)(C + (size_t)(row + 8) * N + n) = make_float2(v2, v3);
                }
            }
        }
    }
}

// ================= gi-GEMM with fused GRU gates epilogue =================
#define GSTR 120
#define GA_HALVES (128 * GSTR)
#define GB_HALVES (96 * GSTR)
#define GATES_SMEM ((GA_HALVES + 2 * GB_HALVES) * 2)
#define GNT 19

__global__ void __launch_bounds__(256, 2) gemm_gates()
{
    extern __shared__ __half gsm[];
    __half* sA = gsm;
    __half* sB = gsm + GA_HALVES;

    const int tid  = threadIdx.x;
    const int warp = tid >> 5, lane = tid & 31;
    const int wm = warp & 3, wn = warp >> 2;
    const int g = lane >> 2, t = lane & 3;
    const int m0 = blockIdx.x * 128;

    const uint32_t sA32 = smem_to_u32(sA);
    const uint32_t sB32 = smem_to_u32(sB);

    auto issueB = [&](int nt) {
        const uint32_t bB = sB32 + (uint32_t)((nt & 1) * GB_HALVES * 2);
#pragma unroll
        for (int i = 0; i < 6; ++i) {
            const int seg = tid + i * 256;
            if (seg < 1344) {
                const int row = seg / 14, q = seg % 14;
                cp_async16(bB + (uint32_t)(row * (GSTR * 2) + q * 16),
                           g_Wc_h + (size_t)(nt * 96 + row) * KN_PAD + q * 8, 16);
            }
        }
        CP_COMMIT();
    };

#pragma unroll
    for (int i = 0; i < 7; ++i) {
        const int seg = tid + i * 256;
        const int row = seg / 14, q = seg % 14;
        cp_async16(sA32 + (uint32_t)(row * (GSTR * 2) + q * 16),
                   g_T_h + (size_t)(m0 + row) * KN_PAD + q * 8, 16);
    }
    {
        const uint32_t bB = sB32;
#pragma unroll
        for (int i = 0; i < 6; ++i) {
            const int seg = tid + i * 256;
            if (seg < 1344) {
                const int row = seg / 14, q = seg % 14;
                cp_async16(bB + (uint32_t)(row * (GSTR * 2) + q * 16),
                           g_Wc_h + (size_t)row * KN_PAD + q * 8, 16);
            }
        }
        CP_COMMIT();
    }
    issueB(1);

#pragma unroll 1
    for (int nt = 0; nt < GNT; ++nt) {
        CP_WAIT(1);
        __syncthreads();

        const __half* a_ = sA;
        const __half* b_ = sB + (nt & 1) * GB_HALVES;

        float acc[2][6][4];
#pragma unroll
        for (int i = 0; i < 2; ++i)
#pragma unroll
            for (int j = 0; j < 6; ++j)
#pragma unroll
                for (int q = 0; q < 4; ++q) acc[i][j][q] = 0.f;

#pragma unroll
        for (int kk = 0; kk < 7; ++kk) {
            const int col = kk * 16 + 2 * t;
            uint32_t af[2][4], bf[6][2];
#pragma unroll
            for (int tm = 0; tm < 2; ++tm) {
                const int r = wm * 32 + tm * 16 + g;
                af[tm][0] = *(const uint32_t*)(a_ + r * GSTR + col);
                af[tm][1] = *(const uint32_t*)(a_ + (r + 8) * GSTR + col);
                af[tm][2] = *(const uint32_t*)(a_ + r * GSTR + col + 8);
                af[tm][3] = *(const uint32_t*)(a_ + (r + 8) * GSTR + col + 8);
            }
#pragma unroll
            for (int tn = 0; tn < 6; ++tn) {
                const int n = wn * 48 + tn * 8 + g;
                bf[tn][0] = *(const uint32_t*)(b_ + n * GSTR + col);
                bf[tn][1] = *(const uint32_t*)(b_ + n * GSTR + col + 8);
            }
#pragma unroll
            for (int tm = 0; tm < 2; ++tm)
#pragma unroll
                for (int tn = 0; tn < 6; ++tn)
                    mma_f16(acc[tm][tn], af[tm], bf[tn]);
        }
        __syncthreads();
        if (nt + 2 < GNT) issueB(nt + 2);
        else              CP_COMMIT();

        const int n0 = nt * 96;
#pragma unroll
        for (int G = 0; G < 2; ++G) {
            const int colbase = n0 + wn * 48 + G * 24;
            const int d = (colbase >= 912);
            const int grp = (colbase - d * 912) / 24;
            const int j0 = grp * 8 + 2 * t;
            const float bh0 = g_bhn[d * 304 + j0];
            const float bh1 = g_bhn[d * 304 + j0 + 1];
            const float cr0 = g_c_r[colbase + 2 * t];
            const float cr1 = g_c_r[colbase + 2 * t + 1];
            const float cz0 = g_c_r[colbase + 8 + 2 * t];
            const float cz1 = g_c_r[colbase + 8 + 2 * t + 1];
            const float cn0 = g_c_r[colbase + 16 + 2 * t];
            const float cn1 = g_c_r[colbase + 16 + 2 * t + 1];
            const bool valid = (j0 < 300);
#pragma unroll
            for (int tm = 0; tm < 2; ++tm) {
#pragma unroll
                for (int rr = 0; rr < 2; ++rr) {
                    const int bt = m0 + wm * 32 + tm * 16 + g + rr * 8;
                    float h0 = 0.f, h1 = 0.f;
                    if (valid) {
                        const int q0 = rr * 2;
                        const float r0 = fsigmoid(acc[tm][3 * G + 0][q0]     + cr0);
                        const float r1 = fsigmoid(acc[tm][3 * G + 0][q0 + 1] + cr1);
                        const float z0 = fsigmoid(acc[tm][3 * G + 1][q0]     + cz0);
                        const float z1 = fsigmoid(acc[tm][3 * G + 1][q0 + 1] + cz1);
                        const float n0_ = acc[tm][3 * G + 2][q0]     + cn0;
                        const float n1_ = acc[tm][3 * G + 2][q0 + 1] + cn1;
                        h0 = (1.f - z0) * ftanh(n0_ + r0 * bh0);
                        h1 = (1.f - z1) * ftanh(n1_ + r1 * bh1);
                    }
                    *(__half2*)(g_hidden_h + (size_t)bt * HPAD + d * 304 + j0) =
                        __floats2half2_rn(h0, h1);
                }
            }
        }
        __syncthreads();
    }
}

// ================= fused scores GEMM + softmax + alpha =================
// grid (NB, 2): CTA computes scores[b, lb*128 .. lb*128+127, 0..511] in smem (fp16,
// same rounding as before), then per-row softmax and column partial-alpha.
#define SC_STR 520
#define ATTN_PIPE_HALVES (2 * (128 + 128) * ASTR)     // 20480
#define ATTN_SC_HALVES   (128 * SC_STR)               // 66560
#define ATTN_SMEM ((ATTN_PIPE_HALVES + ATTN_SC_HALVES) * 2 + 8 * NT * 4)   // 190464 B

__global__ void __launch_bounds__(256, 1) attn_kernel()
{
    extern __shared__ __half asm_[];
    __half* sPipe = asm_;                                   // 2 stages x (A 128x40 | B 128x40)
    __half* ssc   = asm_ + ATTN_PIPE_HALVES;                // [128][520]
    float*  part  = (float*)(asm_ + ATTN_PIPE_HALVES + ATTN_SC_HALVES);  // [8][512]

    const int b  = blockIdx.x;
    const int lb = blockIdx.y;
    const __half* A = g_ctx_h + (size_t)(b * NLQ + lb * 128) * KH_PAD;
    const __half* B = g_hid_h + (size_t)b * NT * KH_PAD;

    const int tid  = threadIdx.x;
    const int warp = tid >> 5, lane = tid & 31;
    const int wm = warp & 3, wn = warp >> 2;
    const int g = lane >> 2, t = lane & 3;

    const uint32_t p32 = smem_to_u32(sPipe);
    const int CH = (KH_PAD + 31) >> 5;                      // 10

#pragma unroll 1
    for (int nt = 0; nt < 4; ++nt) {
        const __half* Bt = B + (size_t)(nt * 128) * KH_PAD;

        auto issue = [&](int c) {
            const int s = c & 1;
            const int kb = c << 5;
            const uint32_t aB = p32 + (uint32_t)s * ((128 + 128) * ASTR * 2);
            const uint32_t bB = aB + (uint32_t)(128 * ASTR * 2);
#pragma unroll
            for (int i = 0; i < 2; ++i) {
                const int seg = tid + i * 256;
                const int row = seg >> 2, q = seg & 3;
                const int k = kb + q * 8;
                const int va = (k + 8 <= KH_PAD);
                cp_async16(aB + (uint32_t)(row * (ASTR * 2) + q * 16),
                           va ? (const void*)(A + (size_t)row * KH_PAD + k) : (const void*)A,
                           va ? 16 : 0);
                cp_async16(bB + (uint32_t)(row * (ASTR * 2) + q * 16),
                           va ? (const void*)(Bt + (size_t)row * KH_PAD + k) : (const void*)Bt,
                           va ? 16 : 0);
            }
            CP_COMMIT();
        };

        float acc[2][8][4];
#pragma unroll
        for (int i = 0; i < 2; ++i)
#pragma unroll
            for (int j = 0; j < 8; ++j)
#pragma unroll
                for (int q = 0; q < 4; ++q) acc[i][j][q] = 0.f;

        issue(0);
        for (int c = 0; c < CH; ++c) {
            if (c + 1 < CH) { issue(c + 1); CP_WAIT(1); }
            else            { CP_WAIT(0); }
            __syncthreads();

            const __half* a_ = sPipe + (size_t)(c & 1) * ((128 + 128) * ASTR);
            const __half* b_ = a_ + 128 * ASTR;

#pragma unroll
            for (int kk = 0; kk < 2; ++kk) {
                const int col = kk * 16 + 2 * t;
                uint32_t af[2][4], bf[8][2];
#pragma unroll
                for (int tm = 0; tm < 2; ++tm) {
                    const int r = wm * 32 + tm * 16 + g;
                    af[tm][0] = *(const uint32_t*)(a_ + r * ASTR + col);
                    af[tm][1] = *(const uint32_t*)(a_ + (r + 8) * ASTR + col);
                    af[tm][2] = *(const uint32_t*)(a_ + r * ASTR + col + 8);
                    af[tm][3] = *(const uint32_t*)(a_ + (r + 8) * ASTR + col + 8);
                }
#pragma unroll
                for (int tn = 0; tn < 8; ++tn) {
                    const int n = wn * 64 + tn * 8 + g;
                    bf[tn][0] = *(const uint32_t*)(b_ + n * ASTR + col);
                    bf[tn][1] = *(const uint32_t*)(b_ + n * ASTR + col + 8);
                }
#pragma unroll
                for (int tm = 0; tm < 2; ++tm)
#pragma unroll
                    for (int tn = 0; tn < 8; ++tn)
                        mma_f16(acc[tm][tn], af[tm], bf[tn]);
            }
            __syncthreads();
        }

        // write fp16 scores to smem (same rounding as the old global store)
#pragma unroll
        for (int tm = 0; tm < 2; ++tm) {
            const int row = wm * 32 + tm * 16 + g;
#pragma unroll
            for (int tn = 0; tn < 8; ++tn) {
                const int n = nt * 128 + wn * 64 + tn * 8 + 2 * t;
                *(__half2*)(ssc + (size_t)row * SC_STR + n) =
                    __floats2half2_rn(acc[tm][tn][0], acc[tm][tn][1]);
                *(__half2*)(ssc + (size_t)(row + 8) * SC_STR + n) =
                    __floats2half2_rn(acc[tm][tn][2], acc[tm][tn][3]);
            }
        }
        __syncthreads();
    }

    // ---- softmax over t per row, accumulate column partials ----
    float pacc[16];
#pragma unroll
    for (int q = 0; q < 16; ++q) pacc[q] = 0.f;

#pragma unroll 1
    for (int i = 0; i < 16; ++i) {
        const int l = warp * 16 + i;
        const __half2* row2 = (const __half2*)(ssc + (size_t)l * SC_STR);
        float v[16], m = -1e30f;
#pragma unroll
        for (int q = 0; q < 8; ++q) {
            float2 f = __half22float2(row2[lane + 32 * q]);
            v[2 * q] = f.x; v[2 * q + 1] = f.y;
            m = fmaxf(m, fmaxf(f.x, f.y));
        }
#pragma unroll
        for (int o = 16; o; o >>= 1) m = fmaxf(m, __shfl_xor_sync(0xffffffffu, m, o));
        float e[16], s = 0.f;
#pragma unroll
        for (int q = 0; q < 16; ++q) { e[q] = fexp2(LOG2E * (v[q] - m)); s += e[q]; }
#pragma unroll
        for (int o = 16; o; o >>= 1) s += __shfl_xor_sync(0xffffffffu, s, o);
        const float rinv = frcp(s);
#pragma unroll
        for (int q = 0; q < 16; ++q) pacc[q] += e[q] * rinv;
    }
#pragma unroll
    for (int q = 0; q < 8; ++q) {
        const int c = 2 * (lane + 32 * q);
        part[warp * NT + c]     = pacc[2 * q];
        part[warp * NT + c + 1] = pacc[2 * q + 1];
    }
    __syncthreads();

#pragma unroll
    for (int h = 0; h < 2; ++h) {
        const int c = tid + h * 256;
        float s = 0.f;
#pragma unroll
        for (int w2 = 0; w2 < 8; ++w2) s += part[w2 * NT + c];
        g_alpha2[(b * 2 + lb) * NT + c] = s;
    }
}

// ---------------- unified fp32 -> fp16 conversions ----------------
#define CVT_N0 ((long)ROWS_BN * KN_PAD)          // nodes
#define CVT_N1 ((long)NB * NLQ * KH_PAD)         // ctx
#define CVT_N2 ((long)300 * KN_PAD)              // W_node
#define CVT_N3 ((long)300 * HPAD)                // W_out
#define CVT_TOTAL (CVT_N0 + CVT_N1 + CVT_N2 + CVT_N3)

__global__ void convert_all(const float* __restrict__ nodes,
                            const float* __restrict__ ctx,
                            const float* __restrict__ Wnode,
                            const float* __restrict__ Wout)
{
    for (long i = blockIdx.x * (long)blockDim.x + threadIdx.x; i < CVT_TOTAL;
         i += (long)gridDim.x * blockDim.x) {
        if (i < CVT_N0) {
            const long r = i / KN_PAD, k = i - r * KN_PAD;
            g_nodes_h[i] = __float2half((k < D_NODE) ? nodes[r * D_NODE + k] : 0.f);
        } else if (i < CVT_N0 + CVT_N1) {
            const long j = i - CVT_N0;
            const long r = j / KH_PAD, k = j - r * KH_PAD;
            g_ctx_h[j] = __float2half((k < D_HID) ? ctx[r * D_HID + k] : 0.f);
        } else if (i < CVT_N0 + CVT_N1 + CVT_N2) {
            const long j = i - CVT_N0 - CVT_N1;
            const long r = j / KN_PAD, k = j - r * KN_PAD;
            g_Wnode_h[j] = __float2half((k < D_NODE) ? Wnode[r * D_NODE + k] : 0.f);
        } else {
            const long j = i - CVT_N0 - CVT_N1 - CVT_N2;
            const long n = j / HPAD, k = j - n * HPAD;
            float v = 0.f;
            if (k < 300)                  v = Wout[n * 600 + k];
            else if (k >= 304 && k < 604) v = Wout[n * 600 + (k - 4)];
            g_Wout_h[j] = __float2half(v);
        }
    }
}

// ---------------- weight combine -> reordered Wc_h / c_r / bhn ----------------
#define CBJ 16
#define COMBINE_SMEM ((30000 + CBJ * 300) * 4)

__global__ void __launch_bounds__(256)
combine_kernel(const float* __restrict__ Wf, const float* __restrict__ bif,
               const float* __restrict__ bhf,
               const float* __restrict__ Wb, const float* __restrict__ bib,
               const float* __restrict__ bhb,
               const float* __restrict__ Wmean, const float* __restrict__ bmean)
{
    extern __shared__ float csm[];
    float* sW   = csm;
    float* srow = csm + 30000;

    const int j0 = blockIdx.x * CBJ;
    const int tid = threadIdx.x;

    for (int i = tid; i < 30000; i += 256) sW[i] = Wmean[i];
    for (int i = tid; i < CBJ * 300; i += 256) {
        const int jj = i / 300, dcol = i % 300;
        const int cnew = j0 + jj;
        const int d = (cnew >= 912);
        const int rem = cnew - d * 912;
        const int grp = rem / 24, gate = (rem % 24) >> 3, pos = rem & 7;
        const int h = grp * 8 + pos;
        float v = 0.f;
        if (h < 300) {
            const int src = gate * 300 + h;
            v = d ? Wb[src * 300 + dcol] : Wf[src * 300 + dcol];
        }
        srow[i] = v;
    }
    __syncthreads();

    for (int idx = tid; idx < CBJ * KN_PAD; idx += 256) {
        const int jj = idx / KN_PAD, k = idx % KN_PAD;
        const int cnew = j0 + jj;
        float s = 0.f;
        if (k < 100) {
            const float* wr = srow + jj * 300;
#pragma unroll 4
            for (int dd = 0; dd < 300; ++dd) s = fmaf(wr[dd], sW[dd * 100 + k], s);
        }
        g_Wc_h[(size_t)cnew * KN_PAD + k] = __float2half(s);
    }
    if (tid < CBJ) {
        const int cnew = j0 + tid;
        const int d = (cnew >= 912);
        const int rem = cnew - d * 912;
        const int grp = rem / 24, gate = (rem % 24) >> 3, pos = rem & 7;
        const int h = grp * 8 + pos;
        float s = 0.f;
        if (h < 300) {
            const int src = gate * 300 + h;
            const float* bih = d ? bib : bif;
            const float* bhh = d ? bhb : bhf;
            s = bih[src];
            const float* wr = srow + tid * 300;
            for (int dd = 0; dd < 300; ++dd) s = fmaf(wr[dd], bmean[dd], s);
            if (gate < 2) s += bhh[src];
            if (gate == 2) g_bhn[d * 304 + h] = bhh[600 + h];
        } else {
            if (gate == 2) g_bhn[d * 304 + h] = 0.f;
        }
        g_c_r[cnew] = s;
    }
}

// ---------------- per-triple averaged node vectors ----------------
__global__ void __launch_bounds__(224) tri_avg(const int* __restrict__ tri)
{
    const int r = threadIdx.x / 28, c = threadIdx.x % 28;
    const int bt = blockIdx.x * 8 + r;
    const int b = bt >> 9;
    const int hN = tri[bt * 3 + 0];
    const int tN = tri[bt * 3 + 2];
    const uint2 vh = ((const uint2*)(g_nodes_h + (size_t)(b * NNODE + hN) * KN_PAD))[c];
    const uint2 vt = ((const uint2*)(g_nodes_h + (size_t)(b * NNODE + tN) * KN_PAD))[c];
    const float2 hx = __half22float2(*(const __half2*)&vh.x);
    const float2 hy = __half22float2(*(const __half2*)&vh.y);
    const float2 tx = __half22float2(*(const __half2*)&vt.x);
    const float2 ty = __half22float2(*(const __half2*)&vt.y);
    __half2 o0 = __floats2half2_rn(0.5f * (hx.x + tx.x), 0.5f * (hx.y + tx.y));
    __half2 o1 = __floats2half2_rn(0.5f * (hy.x + ty.x), 0.5f * (hy.y + ty.y));
    uint2 o;
    o.x = *(uint32_t*)&o0;
    o.y = *(uint32_t*)&o1;
    ((uint2*)(g_T_h + (size_t)bt * KN_PAD))[c] = o;
}

// ---------------- rep = alpha @ hid_ ; layernorm ----------------
__global__ void __launch_bounds__(320) rep_ln_kernel(const float* __restrict__ gamma,
                                                     const float* __restrict__ beta,
                                                     float* __restrict__ out)
{
    const int b = blockIdx.x;
    __shared__ float sal[NT];
    __shared__ float red[2][10];
    const int tid = threadIdx.x;

    for (int t = tid; t < NT; t += 320)
        sal[t] = g_alpha2[(b * 2) * NT + t] + g_alpha2[(b * 2 + 1) * NT + t];
    __syncthreads();

    float acc = 0.f;
    const __half* H = g_hid_h + (size_t)b * NT * KH_PAD;
    if (tid < D_HID) {
        for (int t = 0; t < NT; ++t)
            acc = fmaf(sal[t], __half2float(H[(size_t)t * KH_PAD + tid]), acc);
    }
    float v1 = (tid < D_HID) ? acc : 0.f;
    float v2 = (tid < D_HID) ? acc * acc : 0.f;
#pragma unroll
    for (int o = 16; o; o >>= 1) {
        v1 += __shfl_xor_sync(0xffffffffu, v1, o);
        v2 += __shfl_xor_sync(0xffffffffu, v2, o);
    }
    const int wid = tid >> 5, lane = tid & 31;
    if (lane == 0) { red[0][wid] = v1; red[1][wid] = v2; }
    __syncthreads();
    if (tid == 0) {
        float s1 = 0.f, s2 = 0.f;
        for (int w = 0; w < 10; ++w) { s1 += red[0][w]; s2 += red[1][w]; }
        red[0][0] = s1 / (float)D_HID;
        red[1][0] = s2 / (float)D_HID;
    }
    __syncthreads();
    if (tid < D_HID) {
        float mu = red[0][0];
        float var = red[1][0] - mu * mu;
        out[b * D_HID + tid] = (acc - mu) * rsqrtf(var + 1e-5f) * gamma[tid] + beta[tid];
    }
}

__global__ void zero_tail_kernel(float* __restrict__ out, long start, long end)
{
    long i = start + (long)blockIdx.x * blockDim.x + threadIdx.x;
    if (i < end) out[i] = 0.f;
}

// ---------------- launch ----------------
extern "C" void kernel_launch(void* const* d_in, const int* in_sizes, int n_in,
                              void* d_out, int out_size)
{
    const int o = (in_sizes[3] == 1) ? 1 : 0;

    const float* nodes  = (const float*)d_in[0];
    const float* ctx    = (const float*)d_in[1];
    const int*   tri    = (const int*)d_in[2];
    const float* W_mean = (const float*)d_in[3 + o];
    const float* b_mean = (const float*)d_in[4 + o];
    const float* W_ih_f = (const float*)d_in[5 + o];
    const float* b_ih_f = (const float*)d_in[6 + o];
    const float* b_hh_f = (const float*)d_in[7 + o];
    const float* W_ih_b = (const float*)d_in[8 + o];
    const float* b_ih_b = (const float*)d_in[9 + o];
    const float* b_hh_b = (const float*)d_in[10 + o];
    const float* W_out  = (const float*)d_in[11 + o];
    const float* b_out  = (const float*)d_in[12 + o];
    const float* W_node = (const float*)d_in[13 + o];
    const float* b_node = (const float*)d_in[14 + o];
    const float* gamma  = (const float*)d_in[15 + o];
    const float* beta   = (const float*)d_in[16 + o];
    float* out = (float*)d_out;

    __half *pNodesH, *pWnodeH, *pWoutH, *pHiddenH, *pHidH;
    cudaGetSymbolAddress((void**)&pNodesH,  g_nodes_h);
    cudaGetSymbolAddress((void**)&pWnodeH,  g_Wnode_h);
    cudaGetSymbolAddress((void**)&pWoutH,   g_Wout_h);
    cudaGetSymbolAddress((void**)&pHiddenH, g_hidden_h);
    cudaGetSymbolAddress((void**)&pHidH,    g_hid_h);

    cudaFuncSetAttribute(combine_kernel, cudaFuncAttributeMaxDynamicSharedMemorySize, COMBINE_SMEM);
    cudaFuncSetAttribute(gemm_gates,     cudaFuncAttributeMaxDynamicSharedMemorySize, GATES_SMEM);
    cudaFuncSetAttribute(attn_kernel,    cudaFuncAttributeMaxDynamicSharedMemorySize, ATTN_SMEM);

    // 0. all fp32->fp16 conversions in one launch
    convert_all<<<8192, 256>>>(nodes, ctx, W_node, W_out);

    // 1. combined + reordered weights/biases
    combine_kernel<<<NCOLS / CBJ, 256, COMBINE_SMEM>>>(
        W_ih_f, b_ih_f, b_hh_f, W_ih_b, b_ih_b, b_hh_b, W_mean, b_mean);

    // 2. averaged triple node vectors
    tri_avg<<<ROWS_BT / 8, 224>>>(tri);

    // 3. gi-GEMM + fused GRU gates -> hidden[65536,608]
    gemm_gates<<<ROWS_BT / 128, 256, GATES_SMEM>>>();

    // 4. node_feature (fp32, final)
    {
        dim3 grid((D_HID + BN - 1) / BN, ROWS_BN / BM, 1);
        gemm_f16<false><<<grid, 256>>>(pNodesH, 0, pWnodeH, 0, out + OUT_PATH, 0,
                                       ROWS_BN, D_HID, D_HID, KN_PAD, b_node, 0);
    }
    // 5. hid_[65536,304] = tanh(hidden @ W_out^T + b_out)
    {
        dim3 grid((KH_PAD + BN - 1) / BN, ROWS_BT / BM, 1);
        gemm_f16<true><<<grid, 256>>>(pHiddenH, 0, pWoutH, 0, pHidH, 0,
                                      ROWS_BT, D_HID, KH_PAD, HPAD, b_out, 1);
    }
    // 6. fused scores + softmax + alpha partials
    attn_kernel<<<dim3(NB, 2), 256, ATTN_SMEM>>>();

    // 7. rep + layernorm
    rep_ln_kernel<<<NB, 320>>>(gamma, beta, out);

    // 8. node_mask zeros
    {
        long start = OUT_TAIL_START;
        long end = (long)out_size;
        if (end > start) {
            long n = end - start;
            int blocks = (int)((n + 255) / 256);
            zero_tail_kernel<<<blocks, 256>>>(out, start, end);
        }
    }
}